// round 12
// baseline (speedup 1.0000x reference)
#include <cuda_runtime.h>
#include <cuda_fp16.h>
#include <math.h>
#include <stdint.h>

#define B_   32
#define Q_   300
#define D_   256
#define H_   8
#define C_   32
#define S_   8400
#define TP_  12

// ---------------- scratch (no allocations allowed) ----------------
__device__ __half g_value[(long long)B_ * S_ * D_];  // 137 MB (fp16 value)
__device__ float  g_offs [B_ * Q_ * 192];
__device__ float  g_attn [B_ * Q_ * 96];
__device__ float  g_mid  [B_ * Q_ * D_];
__device__ __half g_wT    [D_ * D_];                 // W_val^T fp16
__device__ __half g_woT_hi[D_ * D_];                 // W_out^T fp16 hi
__device__ __half g_woT_lo[D_ * D_];                 // W_out^T fp16 lo

__device__ __forceinline__ uint32_t smem_u32(const void* p) {
    uint32_t a;
    asm("{ .reg .u64 t; cvta.to.shared.u64 t, %1; cvt.u32.u64 %0, t; }" : "=r"(a) : "l"(p));
    return a;
}
__device__ __forceinline__ void cp_async16(uint32_t dst, const void* src) {
    asm volatile("cp.async.cg.shared.global [%0], [%1], 16;" :: "r"(dst), "l"(src));
}
__device__ __forceinline__ void ldsm_x4(uint32_t& r0, uint32_t& r1, uint32_t& r2,
                                        uint32_t& r3, uint32_t addr) {
    asm volatile("ldmatrix.sync.aligned.m8n8.x4.shared.b16 {%0,%1,%2,%3}, [%4];"
        : "=r"(r0), "=r"(r1), "=r"(r2), "=r"(r3) : "r"(addr));
}
__device__ __forceinline__ void cvt_sts16(uint32_t dst, float4 a, float4 b) {
    __half2 p0 = __floats2half2_rn(a.x, a.y);
    __half2 p1 = __floats2half2_rn(a.z, a.w);
    __half2 p2 = __floats2half2_rn(b.x, b.y);
    __half2 p3 = __floats2half2_rn(b.z, b.w);
    asm volatile("st.shared.v4.b32 [%0], {%1,%2,%3,%4};"
        :: "r"(dst), "r"(*(uint32_t*)&p0), "r"(*(uint32_t*)&p1),
           "r"(*(uint32_t*)&p2), "r"(*(uint32_t*)&p3));
}

// ---------------- prep: transpose weights -> fp16 (z=0: W_val, z=1: W_out hi/lo) ----------------
__global__ void prep_w_kernel(const float* __restrict__ Wv, const float* __restrict__ Wo) {
    __shared__ float t[32][33];
    const float* src = blockIdx.z ? Wo : Wv;
    int bx = blockIdx.x, by = blockIdx.y;
    int tx = threadIdx.x, ty = threadIdx.y;   // 32 x 8
    #pragma unroll
    for (int i = 0; i < 32; i += 8)
        t[ty + i][tx] = src[(size_t)(by * 32 + ty + i) * 256 + bx * 32 + tx];
    __syncthreads();
    #pragma unroll
    for (int i = 0; i < 32; i += 8) {
        int n = bx * 32 + ty + i;
        int k = by * 32 + tx;
        float v = t[tx][ty + i];
        __half h = __float2half_rn(v);
        if (blockIdx.z == 0) {
            g_wT[(size_t)n * 256 + k] = h;
        } else {
            g_woT_hi[(size_t)n * 256 + k] = h;
            g_woT_lo[(size_t)n * 256 + k] = __float2half_rn(v - __half2float(h));
        }
    }
}

// ---------------- mma helper ----------------
__device__ __forceinline__ void mma16816(float* c, const uint32_t* a,
                                         uint32_t b0, uint32_t b1) {
    asm volatile(
        "mma.sync.aligned.m16n8k16.row.col.f32.f16.f16.f32 "
        "{%0,%1,%2,%3}, {%4,%5,%6,%7}, {%8,%9}, {%0,%1,%2,%3};"
        : "+f"(c[0]), "+f"(c[1]), "+f"(c[2]), "+f"(c[3])
        : "r"(a[0]), "r"(a[1]), "r"(a[2]), "r"(a[3]), "r"(b0), "r"(b1));
}

#define RB2  272                 // 128 halves (256B) + 16B pad
#define AB0  0
#define AB1  34816               // 128*272
#define WB0  69632
#define WB1  139264              // WB0 + 256*272
#define VSM_TOT 208896           // WB1 + 69632
#define ROWB 144                 // out-proj kernel row stride (64 halves + pad)
#define OSM_AH 0
#define OSM_AL 18432
#define OSM_WH 36864
#define OSM_WL 55296
#define OSM_TOT 73728
#define NQPROJ 225

// ---------------- fused: qproj (fp32 FFMA) + value GEMM (K-chunk 128, 2 phases) ----
__global__ void __launch_bounds__(512, 1)
fused_main(const float* __restrict__ enc, const float* __restrict__ b_val,
           __half* __restrict__ Cout,
           const float* __restrict__ hidden,
           const float* __restrict__ W_off, const float* __restrict__ b_off,
           const float* __restrict__ W_attn, const float* __restrict__ b_attn)
{
    extern __shared__ char smem[];
    const int tid = threadIdx.x;

    if (blockIdx.x < NQPROJ) {
        // ================= qproj: (9600,256)@(256,288), 512 threads, 8x4 micro ====
        const int K = 256, M = B_ * Q_, N = 288;
        float (*As)[132] = (float(*)[132])(smem);
        float (*Ws)[128] = (float(*)[128])(smem + 16 * 132 * 4);

        const int tx  = tid & 31;
        const int ty  = tid >> 5;
        const int m0  = (blockIdx.x / 3) * 128;
        const int n0  = (blockIdx.x % 3) * 128;

        float acc[8][4];
        #pragma unroll
        for (int i = 0; i < 8; i++)
            #pragma unroll
            for (int j = 0; j < 4; j++) acc[i][j] = 0.f;

        for (int kt = 0; kt < K; kt += 16) {
            {
                int row = tid >> 2;
                int kq  = (tid & 3) * 4;
                float4 v = make_float4(0.f, 0.f, 0.f, 0.f);
                int gr = m0 + row;
                if (gr < M)
                    v = *(const float4*)(hidden + (size_t)gr * K + kt + kq);
                As[kq + 0][row] = v.x;
                As[kq + 1][row] = v.y;
                As[kq + 2][row] = v.z;
                As[kq + 3][row] = v.w;
            }
            {
                int kr  = tid >> 5;
                int c4  = (tid & 31) * 4;
                float4 v = make_float4(0.f, 0.f, 0.f, 0.f);
                int gc = n0 + c4;
                if (gc < 192)
                    v = *(const float4*)(W_off + (size_t)(kt + kr) * 192 + gc);
                else if (gc < N)
                    v = *(const float4*)(W_attn + (size_t)(kt + kr) * 96 + gc - 192);
                *(float4*)&Ws[kr][c4] = v;
            }
            __syncthreads();

            #pragma unroll
            for (int k = 0; k < 16; k++) {
                float a[8], b[4];
                *(float4*)&a[0] = *(const float4*)&As[k][ty * 8];
                *(float4*)&a[4] = *(const float4*)&As[k][ty * 8 + 4];
                *(float4*)&b[0] = *(const float4*)&Ws[k][tx * 4];
                #pragma unroll
                for (int i = 0; i < 8; i++)
                    #pragma unroll
                    for (int j = 0; j < 4; j++)
                        acc[i][j] = fmaf(a[i], b[j], acc[i][j]);
            }
            __syncthreads();
        }

        #pragma unroll
        for (int i = 0; i < 8; i++) {
            int gr = m0 + ty * 8 + i;
            if (gr >= M) continue;
            int gc = n0 + tx * 4;
            if (gc < 192) {
                float4 o;
                o.x = acc[i][0] + b_off[gc + 0];
                o.y = acc[i][1] + b_off[gc + 1];
                o.z = acc[i][2] + b_off[gc + 2];
                o.w = acc[i][3] + b_off[gc + 3];
                *(float4*)(g_offs + (size_t)gr * 192 + gc) = o;
            } else if (gc < N) {
                int ga = gc - 192;
                float4 o;
                o.x = acc[i][0] + b_attn[ga + 0];
                o.y = acc[i][1] + b_attn[ga + 1];
                o.z = acc[i][2] + b_attn[ga + 2];
                o.w = acc[i][3] + b_attn[ga + 3];
                *(float4*)(g_attn + (size_t)gr * 96 + ga) = o;
            }
        }
        return;
    }

    // ================= value GEMM: 128M x 256N, K-chunk 128, 2 phases ============
    const int id  = blockIdx.x - NQPROJ;
    const int wid = tid >> 5, lid = tid & 31;
    const int g   = lid >> 2;
    const int t2  = (lid & 3) * 2;
    const int wm  = (wid & 3) * 32;
    const int wn  = (wid >> 2) * 64;
    const int m0  = id * 128;

    const uint32_t sb = smem_u32(smem);
    const int arow = tid >> 2, aq = tid & 3;       // A: 128 rows x 4 quarters (32 fl)
    const int wrow = tid >> 1, whlf = tid & 1;     // W: 256 rows x 2 halves (128B)

    const float* asrc = enc + (size_t)(m0 + arow) * 256 + aq * 32;
    const char*  wsrc = (const char*)g_wT + (size_t)wrow * 512 + whlf * 128;
    const uint32_t adst[2] = { sb + AB0 + (uint32_t)(arow * RB2 + aq * 64),
                               sb + AB1 + (uint32_t)(arow * RB2 + aq * 64) };
    const uint32_t wdst[2] = { sb + WB0 + (uint32_t)(wrow * RB2 + whlf * 128),
                               sb + WB1 + (uint32_t)(wrow * RB2 + whlf * 128) };

    const uint32_t lmoff = (uint32_t)(((lid & 7) + ((lid >> 3) & 1) * 8) * RB2
                                      + (lid >> 4) * 16);
    const uint32_t albase[2] = { sb + AB0 + (uint32_t)(wm * RB2) + lmoff,
                                 sb + AB1 + (uint32_t)(wm * RB2) + lmoff };
    const uint32_t wlbase[2] = { sb + WB0 + (uint32_t)(wn * RB2) + lmoff,
                                 sb + WB1 + (uint32_t)(wn * RB2) + lmoff };

    float acc[2][8][4];
    #pragma unroll
    for (int i = 0; i < 2; i++)
        #pragma unroll
        for (int j = 0; j < 8; j++)
            #pragma unroll
            for (int k = 0; k < 4; k++) acc[i][j][k] = 0.f;

    // ---- prologue: stage chunk 0 (k = aq*32 + [0,32) of first 128) ----
    #pragma unroll
    for (int j = 0; j < 8; j++)
        cp_async16(wdst[0] + j * 16, wsrc + j * 16);
    asm volatile("cp.async.commit_group;");
    {
        float4 av[4];
        #pragma unroll
        for (int j = 0; j < 4; j++) av[j] = *(const float4*)(asrc + j * 4);
        cvt_sts16(adst[0],      av[0], av[1]);
        cvt_sts16(adst[0] + 16, av[2], av[3]);
        #pragma unroll
        for (int j = 0; j < 4; j++) av[j] = *(const float4*)(asrc + 16 + j * 4);
        cvt_sts16(adst[0] + 32, av[0], av[1]);
        cvt_sts16(adst[0] + 48, av[2], av[3]);
    }
    asm volatile("cp.async.wait_group 0;" ::: "memory");
    __syncthreads();

    #pragma unroll
    for (int ch = 0; ch < 2; ch++) {
        const int cur = ch;
        float4 av[4];
        if (ch == 0) {
            #pragma unroll
            for (int j = 0; j < 8; j++)
                cp_async16(wdst[1] + j * 16, wsrc + 256 + j * 16);
            asm volatile("cp.async.commit_group;");
            // FIX: chunk 1 of A lives at +128 floats (k = 128..255)
            #pragma unroll
            for (int j = 0; j < 4; j++)
                av[j] = *(const float4*)(asrc + 128 + j * 4);
        }

        // ---- first half of MMAs (ks 0..3) ----
        #pragma unroll
        for (int ks = 0; ks < 4; ks++) {
            uint32_t ah[2][4];
            ldsm_x4(ah[0][0], ah[0][1], ah[0][2], ah[0][3], albase[cur] + ks * 32);
            ldsm_x4(ah[1][0], ah[1][1], ah[1][2], ah[1][3],
                    albase[cur] + 16 * RB2 + ks * 32);
            uint32_t bw[8][2];
            #pragma unroll
            for (int nfp = 0; nfp < 4; nfp++) {
                uint32_t q0, q1, q2, q3;
                ldsm_x4(q0, q1, q2, q3, wlbase[cur] + nfp * 16 * RB2 + ks * 32);
                bw[2*nfp][0]   = q0;  bw[2*nfp][1]   = q2;
                bw[2*nfp+1][0] = q1;  bw[2*nfp+1][1] = q3;
            }
            #pragma unroll
            for (int nf = 0; nf < 8; nf++) {
                mma16816(acc[0][nf], ah[0], bw[nf][0], bw[nf][1]);
                mma16816(acc[1][nf], ah[1], bw[nf][0], bw[nf][1]);
            }
        }

        if (ch == 0) {
            cvt_sts16(adst[1],      av[0], av[1]);
            cvt_sts16(adst[1] + 16, av[2], av[3]);
            // FIX: second 16 floats of chunk-1 quarter at +144
            #pragma unroll
            for (int j = 0; j < 4; j++)
                av[j] = *(const float4*)(asrc + 144 + j * 4);
        }

        // ---- second half of MMAs (ks 4..7) ----
        #pragma unroll
        for (int ks = 4; ks < 8; ks++) {
            uint32_t ah[2][4];
            ldsm_x4(ah[0][0], ah[0][1], ah[0][2], ah[0][3], albase[cur] + ks * 32);
            ldsm_x4(ah[1][0], ah[1][1], ah[1][2], ah[1][3],
                    albase[cur] + 16 * RB2 + ks * 32);
            uint32_t bw[8][2];
            #pragma unroll
            for (int nfp = 0; nfp < 4; nfp++) {
                uint32_t q0, q1, q2, q3;
                ldsm_x4(q0, q1, q2, q3, wlbase[cur] + nfp * 16 * RB2 + ks * 32);
                bw[2*nfp][0]   = q0;  bw[2*nfp][1]   = q2;
                bw[2*nfp+1][0] = q1;  bw[2*nfp+1][1] = q3;
            }
            #pragma unroll
            for (int nf = 0; nf < 8; nf++) {
                mma16816(acc[0][nf], ah[0], bw[nf][0], bw[nf][1]);
                mma16816(acc[1][nf], ah[1], bw[nf][0], bw[nf][1]);
            }
        }

        if (ch == 0) {
            cvt_sts16(adst[1] + 32, av[0], av[1]);
            cvt_sts16(adst[1] + 48, av[2], av[3]);
            asm volatile("cp.async.wait_group 0;" ::: "memory");
            __syncthreads();
        }
    }

    // ---- epilogue: +bias, convert fp16, store ----
    #pragma unroll
    for (int mf = 0; mf < 2; mf++) {
        __half* r0 = Cout + (size_t)(m0 + wm + mf * 16 + g) * 256 + wn;
        __half* r8 = r0 + (size_t)8 * 256;
        #pragma unroll
        for (int nf = 0; nf < 8; nf++) {
            float2 bv = *(const float2*)(b_val + wn + nf * 8 + t2);
            *(__half2*)(r0 + nf * 8 + t2) =
                __floats2half2_rn(acc[mf][nf][0] + bv.x, acc[mf][nf][1] + bv.y);
            *(__half2*)(r8 + nf * 8 + t2) =
                __floats2half2_rn(acc[mf][nf][2] + bv.x, acc[mf][nf][3] + bv.y);
        }
    }
}

// ---------------- out projection: mma fp16 3-product (AhWh + AlWh + AhWl) ----------------
__global__ void __launch_bounds__(256, 2)
out_gemm_mma(const float* __restrict__ A, const float* __restrict__ bias,
             float* __restrict__ Cout)
{
    extern __shared__ char smem[];
    const int tid = threadIdx.x;
    const int wid = tid >> 5, lid = tid & 31;
    const int g   = lid >> 2;
    const int t2  = (lid & 3) * 2;
    const int wm  = (wid & 3) * 32;
    const int wn  = (wid >> 2) * 64;
    const int m0  = blockIdx.x * 128;
    const int n0  = blockIdx.y * 128;

    float acc[2][8][4];
    #pragma unroll
    for (int i = 0; i < 2; i++)
        #pragma unroll
        for (int j = 0; j < 8; j++)
            #pragma unroll
            for (int k = 0; k < 4; k++) acc[i][j][k] = 0.f;

    const int lrow  = tid >> 1;
    const int lhalf = tid & 1;

    for (int ch = 0; ch < 4; ch++) {
        {
            const float4* ap = (const float4*)(A + (size_t)(m0 + lrow) * 256 + ch * 64 + lhalf * 32);
            char* ahb = smem + OSM_AH + lrow * ROWB + lhalf * 64;
            char* alb = smem + OSM_AL + lrow * ROWB + lhalf * 64;
            #pragma unroll
            for (int j = 0; j < 4; j++) {
                float4 v0 = ap[2 * j], v1 = ap[2 * j + 1];
                float f[8] = {v0.x, v0.y, v0.z, v0.w, v1.x, v1.y, v1.z, v1.w};
                unsigned hb[8], lb[8];
                #pragma unroll
                for (int e = 0; e < 8; e++) {
                    __half h = __float2half_rn(f[e]);
                    hb[e] = __half_as_ushort(h);
                    lb[e] = __half_as_ushort(__float2half_rn(f[e] - __half2float(h)));
                }
                *(uint4*)(ahb + j * 16) = make_uint4(hb[0] | (hb[1] << 16), hb[2] | (hb[3] << 16),
                                                    hb[4] | (hb[5] << 16), hb[6] | (hb[7] << 16));
                *(uint4*)(alb + j * 16) = make_uint4(lb[0] | (lb[1] << 16), lb[2] | (lb[3] << 16),
                                                    lb[4] | (lb[5] << 16), lb[6] | (lb[7] << 16));
            }
        }
        {
            const uint4* wh = (const uint4*)((const char*)g_woT_hi + (size_t)(n0 + lrow) * 512 + ch * 128 + lhalf * 64);
            const uint4* wl = (const uint4*)((const char*)g_woT_lo + (size_t)(n0 + lrow) * 512 + ch * 128 + lhalf * 64);
            char* whb = smem + OSM_WH + lrow * ROWB + lhalf * 64;
            char* wlb = smem + OSM_WL + lrow * ROWB + lhalf * 64;
            #pragma unroll
            for (int j = 0; j < 4; j++) {
                *(uint4*)(whb + j * 16) = wh[j];
                *(uint4*)(wlb + j * 16) = wl[j];
            }
        }
        __syncthreads();

        #pragma unroll
        for (int ks = 0; ks < 4; ks++) {
            const int koff = (ks * 16 + t2) * 2;
            uint32_t ah[2][4], al[2][4];
            #pragma unroll
            for (int mf = 0; mf < 2; mf++) {
                const char* pa = smem + (wm + mf * 16 + g) * ROWB + koff;
                ah[mf][0] = *(const uint32_t*)(pa + OSM_AH);
                ah[mf][1] = *(const uint32_t*)(pa + OSM_AH + 8 * ROWB);
                ah[mf][2] = *(const uint32_t*)(pa + OSM_AH + 16);
                ah[mf][3] = *(const uint32_t*)(pa + OSM_AH + 8 * ROWB + 16);
                al[mf][0] = *(const uint32_t*)(pa + OSM_AL);
                al[mf][1] = *(const uint32_t*)(pa + OSM_AL + 8 * ROWB);
                al[mf][2] = *(const uint32_t*)(pa + OSM_AL + 16);
                al[mf][3] = *(const uint32_t*)(pa + OSM_AL + 8 * ROWB + 16);
            }
            #pragma unroll
            for (int nf = 0; nf < 8; nf++) {
                const char* pb = smem + (wn + nf * 8 + g) * ROWB + koff;
                uint32_t bh0 = *(const uint32_t*)(pb + OSM_WH);
                uint32_t bh1 = *(const uint32_t*)(pb + OSM_WH + 16);
                uint32_t bl0 = *(const uint32_t*)(pb + OSM_WL);
                uint32_t bl1 = *(const uint32_t*)(pb + OSM_WL + 16);
                mma16816(acc[0][nf], ah[0], bh0, bh1);
                mma16816(acc[1][nf], ah[1], bh0, bh1);
                mma16816(acc[0][nf], al[0], bh0, bh1);
                mma16816(acc[1][nf], al[1], bh0, bh1);
                mma16816(acc[0][nf], ah[0], bl0, bl1);
                mma16816(acc[1][nf], ah[1], bl0, bl1);
            }
        }
        __syncthreads();
    }

    #pragma unroll
    for (int mf = 0; mf < 2; mf++) {
        float* r0 = Cout + (size_t)(m0 + wm + mf * 16 + g) * 256 + n0 + wn;
        float* r8 = r0 + (size_t)8 * 256;
        #pragma unroll
        for (int nf = 0; nf < 8; nf++) {
            float2 bv = *(const float2*)(bias + n0 + wn + nf * 8 + t2);
            float2 o0, o1;
            o0.x = acc[mf][nf][0] + bv.x;  o0.y = acc[mf][nf][1] + bv.y;
            o1.x = acc[mf][nf][2] + bv.x;  o1.y = acc[mf][nf][3] + bv.y;
            *(float2*)(r0 + nf * 8 + t2) = o0;
            *(float2*)(r8 + nf * 8 + t2) = o1;
        }
    }
}

// ---------------- softmax + deformable sampling (128 thr, half2 channels) ----------------
__global__ void __launch_bounds__(128)
sample_kernel(const float* __restrict__ refp, float* __restrict__ mid)
{
    const int bq  = blockIdx.x;
    const int b   = bq / Q_;
    const int tid = threadIdx.x;
    const int h   = tid >> 4;
    const int c2  = tid & 15;

    __shared__ float s_off[192];
    __shared__ float s_att[96];
    __shared__ float s_r[4];
    __shared__ int   s_idx[96 * 4];
    __shared__ float s_w[96 * 4];

    for (int i = tid; i < 192; i += 128) s_off[i] = g_offs[bq * 192 + i];
    if (tid < 96) s_att[tid] = g_attn[bq * 96 + tid];
    if (tid < 4)  s_r[tid]   = refp[bq * 4 + tid];
    __syncthreads();

    if (tid < 8) {
        float mx = -1e30f;
        #pragma unroll
        for (int p = 0; p < TP_; p++) mx = fmaxf(mx, s_att[tid * TP_ + p]);
        float sm = 0.f;
        #pragma unroll
        for (int p = 0; p < TP_; p++) {
            float e = expf(s_att[tid * TP_ + p] - mx);
            s_att[tid * TP_ + p] = e;
            sm += e;
        }
        float inv = 1.f / sm;
        #pragma unroll
        for (int p = 0; p < TP_; p++) s_att[tid * TP_ + p] *= inv;
    }
    __syncthreads();

    if (tid < 96) {
        const int p = tid % TP_;
        const int l = p >> 2;
        const int Wd = (l == 0) ? 80 : (l == 1) ? 40 : 20;
        const int st = (l == 0) ? 0  : (l == 1) ? 6400 : 8000;
        const float rx = s_r[0], ry = s_r[1];
        const float rw = s_r[2] * 0.125f;
        const float rh = s_r[3] * 0.125f;
        const float a  = s_att[tid];

        const float gx = (rx + s_off[tid * 2 + 0] * rw) * (float)Wd - 0.5f;
        const float gy = (ry + s_off[tid * 2 + 1] * rh) * (float)Wd - 0.5f;
        const float x0f = floorf(gx), y0f = floorf(gy);
        const float fx = gx - x0f, fy = gy - y0f;
        const int ix0 = (int)x0f, iy0 = (int)y0f;
        const int ix1 = ix0 + 1,  iy1 = iy0 + 1;
        const bool vx0 = (ix0 >= 0) & (ix0 < Wd);
        const bool vx1 = (ix1 >= 0) & (ix1 < Wd);
        const bool vy0 = (iy0 >= 0) & (iy0 < Wd);
        const bool vy1 = (iy1 >= 0) & (iy1 < Wd);
        const int ix0c = min(max(ix0, 0), Wd - 1);
        const int ix1c = min(max(ix1, 0), Wd - 1);
        const int iy0c = min(max(iy0, 0), Wd - 1);
        const int iy1c = min(max(iy1, 0), Wd - 1);

        s_w[tid * 4 + 0] = (vx0 & vy0) ? (1.f - fx) * (1.f - fy) * a : 0.f;
        s_w[tid * 4 + 1] = (vx1 & vy0) ? fx * (1.f - fy) * a : 0.f;
        s_w[tid * 4 + 2] = (vx0 & vy1) ? (1.f - fx) * fy * a : 0.f;
        s_w[tid * 4 + 3] = (vx1 & vy1) ? fx * fy * a : 0.f;
        s_idx[tid * 4 + 0] = (st + iy0c * Wd + ix0c) * D_;
        s_idx[tid * 4 + 1] = (st + iy0c * Wd + ix1c) * D_;
        s_idx[tid * 4 + 2] = (st + iy1c * Wd + ix0c) * D_;
        s_idx[tid * 4 + 3] = (st + iy1c * Wd + ix1c) * D_;
    }
    __syncthreads();

    const __half* vb = g_value + (size_t)b * S_ * D_ + h * C_ + c2 * 2;

    float accx = 0.f, accy = 0.f;
    #pragma unroll
    for (int p = 0; p < TP_; p++) {
        const int e = (h * TP_ + p) * 4;
        const int   i0 = s_idx[e], i1 = s_idx[e + 1], i2 = s_idx[e + 2], i3 = s_idx[e + 3];
        const float w0 = s_w[e],   w1 = s_w[e + 1],   w2 = s_w[e + 2],   w3 = s_w[e + 3];
        float2 v0 = __half22float2(*(const __half2*)(vb + i0));
        float2 v1 = __half22float2(*(const __half2*)(vb + i1));
        float2 v2 = __half22float2(*(const __half2*)(vb + i2));
        float2 v3 = __half22float2(*(const __half2*)(vb + i3));
        accx = fmaf(w0, v0.x, accx);  accy = fmaf(w0, v0.y, accy);
        accx = fmaf(w1, v1.x, accx);  accy = fmaf(w1, v1.y, accy);
        accx = fmaf(w2, v2.x, accx);  accy = fmaf(w2, v2.y, accy);
        accx = fmaf(w3, v3.x, accx);  accy = fmaf(w3, v3.y, accy);
    }
    *(float2*)(mid + (size_t)bq * D_ + h * C_ + c2 * 2) = make_float2(accx, accy);
}

// ---------------- launcher ----------------
extern "C" void kernel_launch(void* const* d_in, const int* in_sizes, int n_in,
                              void* d_out, int out_size)
{
    (void)in_sizes; (void)n_in; (void)out_size;
    const float* hidden = (const float*)d_in[0];
    const float* enc    = (const float*)d_in[1];
    const float* refp   = (const float*)d_in[2];
    const float* W_off  = (const float*)d_in[3];
    const float* b_off  = (const float*)d_in[4];
    const float* W_attn = (const float*)d_in[5];
    const float* b_attn = (const float*)d_in[6];
    const float* W_val  = (const float*)d_in[7];
    const float* b_val  = (const float*)d_in[8];
    const float* W_out  = (const float*)d_in[9];
    const float* b_out  = (const float*)d_in[10];
    float* out = (float*)d_out;

    __half* p_value;
    float*  p_mid;
    cudaGetSymbolAddress((void**)&p_value, g_value);
    cudaGetSymbolAddress((void**)&p_mid,   g_mid);

    cudaFuncSetAttribute(fused_main,   cudaFuncAttributeMaxDynamicSharedMemorySize, VSM_TOT);
    cudaFuncSetAttribute(out_gemm_mma, cudaFuncAttributeMaxDynamicSharedMemorySize, OSM_TOT);

    // 0) transpose + fp16-convert W_val (z=0) and W_out hi/lo (z=1)
    prep_w_kernel<<<dim3(8, 8, 2), dim3(32, 8)>>>(W_val, W_out);

    // 1) fused: qproj blocks (first 225) + 2-phase value GEMM blocks (2100)
    fused_main<<<NQPROJ + B_ * S_ / 128, 512, VSM_TOT>>>(
        enc, b_val, p_value, hidden, W_off, b_off, W_attn, b_attn);

    // 2) softmax + bilinear gather + weighted sum
    sample_kernel<<<B_ * Q_, 128>>>(refp, p_mid);

    // 3) output projection on tensor cores (3-product)
    out_gemm_mma<<<dim3(B_ * Q_ / 128, 2), 256, OSM_TOT>>>(p_mid, b_out, out);
}

// round 13
// speedup vs baseline: 1.0121x; 1.0121x over previous
#include <cuda_runtime.h>
#include <cuda_fp16.h>
#include <math.h>
#include <stdint.h>

#define B_   32
#define Q_   300
#define D_   256
#define H_   8
#define C_   32
#define S_   8400
#define TP_  12

// ---------------- scratch (no allocations allowed) ----------------
__device__ __half g_value[(long long)B_ * S_ * D_];  // 137 MB (fp16 value)
__device__ float  g_offs [B_ * Q_ * 192];
__device__ float  g_attn [B_ * Q_ * 96];
__device__ float  g_mid  [B_ * Q_ * D_];
__device__ __half g_wT    [D_ * D_];                 // W_val^T fp16
__device__ __half g_woT_hi[D_ * D_];                 // W_out^T fp16 hi
__device__ __half g_woT_lo[D_ * D_];                 // W_out^T fp16 lo

__device__ __forceinline__ uint32_t smem_u32(const void* p) {
    uint32_t a;
    asm("{ .reg .u64 t; cvta.to.shared.u64 t, %1; cvt.u32.u64 %0, t; }" : "=r"(a) : "l"(p));
    return a;
}
__device__ __forceinline__ void cp_async16(uint32_t dst, const void* src) {
    asm volatile("cp.async.cg.shared.global [%0], [%1], 16;" :: "r"(dst), "l"(src));
}
__device__ __forceinline__ void ldsm_x4(uint32_t& r0, uint32_t& r1, uint32_t& r2,
                                        uint32_t& r3, uint32_t addr) {
    asm volatile("ldmatrix.sync.aligned.m8n8.x4.shared.b16 {%0,%1,%2,%3}, [%4];"
        : "=r"(r0), "=r"(r1), "=r"(r2), "=r"(r3) : "r"(addr));
}
__device__ __forceinline__ void cvt_sts16(uint32_t dst, float4 a, float4 b) {
    __half2 p0 = __floats2half2_rn(a.x, a.y);
    __half2 p1 = __floats2half2_rn(a.z, a.w);
    __half2 p2 = __floats2half2_rn(b.x, b.y);
    __half2 p3 = __floats2half2_rn(b.z, b.w);
    asm volatile("st.shared.v4.b32 [%0], {%1,%2,%3,%4};"
        :: "r"(dst), "r"(*(uint32_t*)&p0), "r"(*(uint32_t*)&p1),
           "r"(*(uint32_t*)&p2), "r"(*(uint32_t*)&p3));
}

// ---------------- prep: transpose weights -> fp16 (z=0: W_val, z=1: W_out hi/lo) ----------------
__global__ void prep_w_kernel(const float* __restrict__ Wv, const float* __restrict__ Wo) {
    __shared__ float t[32][33];
    const float* src = blockIdx.z ? Wo : Wv;
    int bx = blockIdx.x, by = blockIdx.y;
    int tx = threadIdx.x, ty = threadIdx.y;   // 32 x 8
    #pragma unroll
    for (int i = 0; i < 32; i += 8)
        t[ty + i][tx] = src[(size_t)(by * 32 + ty + i) * 256 + bx * 32 + tx];
    __syncthreads();
    #pragma unroll
    for (int i = 0; i < 32; i += 8) {
        int n = bx * 32 + ty + i;
        int k = by * 32 + tx;
        float v = t[tx][ty + i];
        __half h = __float2half_rn(v);
        if (blockIdx.z == 0) {
            g_wT[(size_t)n * 256 + k] = h;
        } else {
            g_woT_hi[(size_t)n * 256 + k] = h;
            g_woT_lo[(size_t)n * 256 + k] = __float2half_rn(v - __half2float(h));
        }
    }
}

// ---------------- mma helper ----------------
__device__ __forceinline__ void mma16816(float* c, const uint32_t* a,
                                         uint32_t b0, uint32_t b1) {
    asm volatile(
        "mma.sync.aligned.m16n8k16.row.col.f32.f16.f16.f32 "
        "{%0,%1,%2,%3}, {%4,%5,%6,%7}, {%8,%9}, {%0,%1,%2,%3};"
        : "+f"(c[0]), "+f"(c[1]), "+f"(c[2]), "+f"(c[3])
        : "r"(a[0]), "r"(a[1]), "r"(a[2]), "r"(a[3]), "r"(b0), "r"(b1));
}

#define RB2  272                 // 128 halves (256B) + 16B pad
#define AB0  0
#define AB1  34816               // 128*272
#define WB0  69632
#define WB1  139264              // WB0 + 256*272
#define VSM_TOT 208896           // WB1 + 69632
#define ROWB 144                 // out-proj kernel row stride (64 halves + pad)
#define OSM_AH 0
#define OSM_AL 18432
#define OSM_WH 36864
#define OSM_WL 55296
#define OSM_TOT 73728
#define NQPROJ 225

// ---------------- fused: qproj (fp32 FFMA) + value GEMM (K-chunk 128, 2 phases) ----
__global__ void __launch_bounds__(512, 1)
fused_main(const float* __restrict__ enc, const float* __restrict__ b_val,
           __half* __restrict__ Cout,
           const float* __restrict__ hidden,
           const float* __restrict__ W_off, const float* __restrict__ b_off,
           const float* __restrict__ W_attn, const float* __restrict__ b_attn)
{
    extern __shared__ char smem[];
    const int tid = threadIdx.x;

    if (blockIdx.x < NQPROJ) {
        // ================= qproj: (9600,256)@(256,288), 512 threads, 8x4 micro ====
        const int K = 256, M = B_ * Q_, N = 288;
        float (*As)[132] = (float(*)[132])(smem);
        float (*Ws)[128] = (float(*)[128])(smem + 16 * 132 * 4);

        const int tx  = tid & 31;
        const int ty  = tid >> 5;
        const int m0  = (blockIdx.x / 3) * 128;
        const int n0  = (blockIdx.x % 3) * 128;

        float acc[8][4];
        #pragma unroll
        for (int i = 0; i < 8; i++)
            #pragma unroll
            for (int j = 0; j < 4; j++) acc[i][j] = 0.f;

        for (int kt = 0; kt < K; kt += 16) {
            {
                int row = tid >> 2;
                int kq  = (tid & 3) * 4;
                float4 v = make_float4(0.f, 0.f, 0.f, 0.f);
                int gr = m0 + row;
                if (gr < M)
                    v = *(const float4*)(hidden + (size_t)gr * K + kt + kq);
                As[kq + 0][row] = v.x;
                As[kq + 1][row] = v.y;
                As[kq + 2][row] = v.z;
                As[kq + 3][row] = v.w;
            }
            {
                int kr  = tid >> 5;
                int c4  = (tid & 31) * 4;
                float4 v = make_float4(0.f, 0.f, 0.f, 0.f);
                int gc = n0 + c4;
                if (gc < 192)
                    v = *(const float4*)(W_off + (size_t)(kt + kr) * 192 + gc);
                else if (gc < N)
                    v = *(const float4*)(W_attn + (size_t)(kt + kr) * 96 + gc - 192);
                *(float4*)&Ws[kr][c4] = v;
            }
            __syncthreads();

            #pragma unroll
            for (int k = 0; k < 16; k++) {
                float a[8], b[4];
                *(float4*)&a[0] = *(const float4*)&As[k][ty * 8];
                *(float4*)&a[4] = *(const float4*)&As[k][ty * 8 + 4];
                *(float4*)&b[0] = *(const float4*)&Ws[k][tx * 4];
                #pragma unroll
                for (int i = 0; i < 8; i++)
                    #pragma unroll
                    for (int j = 0; j < 4; j++)
                        acc[i][j] = fmaf(a[i], b[j], acc[i][j]);
            }
            __syncthreads();
        }

        #pragma unroll
        for (int i = 0; i < 8; i++) {
            int gr = m0 + ty * 8 + i;
            if (gr >= M) continue;
            int gc = n0 + tx * 4;
            if (gc < 192) {
                float4 o;
                o.x = acc[i][0] + b_off[gc + 0];
                o.y = acc[i][1] + b_off[gc + 1];
                o.z = acc[i][2] + b_off[gc + 2];
                o.w = acc[i][3] + b_off[gc + 3];
                *(float4*)(g_offs + (size_t)gr * 192 + gc) = o;
            } else if (gc < N) {
                int ga = gc - 192;
                float4 o;
                o.x = acc[i][0] + b_attn[ga + 0];
                o.y = acc[i][1] + b_attn[ga + 1];
                o.z = acc[i][2] + b_attn[ga + 2];
                o.w = acc[i][3] + b_attn[ga + 3];
                *(float4*)(g_attn + (size_t)gr * 96 + ga) = o;
            }
        }
        return;
    }

    // ================= value GEMM: 128M x 256N, K-chunk 128, 2 phases ============
    const int id  = blockIdx.x - NQPROJ;
    const int wid = tid >> 5, lid = tid & 31;
    const int g   = lid >> 2;
    const int t2  = (lid & 3) * 2;
    const int wm  = (wid & 3) * 32;
    const int wn  = (wid >> 2) * 64;
    const int m0  = id * 128;

    const uint32_t sb = smem_u32(smem);
    const int arow = tid >> 2, aq = tid & 3;       // A: 128 rows x 4 quarters (32 fl)
    const int wrow = tid >> 1, whlf = tid & 1;     // W: 256 rows x 2 halves (128B)

    const float* asrc = enc + (size_t)(m0 + arow) * 256 + aq * 32;
    const char*  wsrc = (const char*)g_wT + (size_t)wrow * 512 + whlf * 128;
    const uint32_t adst[2] = { sb + AB0 + (uint32_t)(arow * RB2 + aq * 64),
                               sb + AB1 + (uint32_t)(arow * RB2 + aq * 64) };
    const uint32_t wdst[2] = { sb + WB0 + (uint32_t)(wrow * RB2 + whlf * 128),
                               sb + WB1 + (uint32_t)(wrow * RB2 + whlf * 128) };

    const uint32_t lmoff = (uint32_t)(((lid & 7) + ((lid >> 3) & 1) * 8) * RB2
                                      + (lid >> 4) * 16);
    const uint32_t albase[2] = { sb + AB0 + (uint32_t)(wm * RB2) + lmoff,
                                 sb + AB1 + (uint32_t)(wm * RB2) + lmoff };
    const uint32_t wlbase[2] = { sb + WB0 + (uint32_t)(wn * RB2) + lmoff,
                                 sb + WB1 + (uint32_t)(wn * RB2) + lmoff };

    float acc[2][8][4];
    #pragma unroll
    for (int i = 0; i < 2; i++)
        #pragma unroll
        for (int j = 0; j < 8; j++)
            #pragma unroll
            for (int k = 0; k < 4; k++) acc[i][j][k] = 0.f;

    // ---- prologue: stage chunk 0 (k = aq*32 + [0,32) of first 128) ----
    #pragma unroll
    for (int j = 0; j < 8; j++)
        cp_async16(wdst[0] + j * 16, wsrc + j * 16);
    asm volatile("cp.async.commit_group;");
    {
        float4 av[4];
        #pragma unroll
        for (int j = 0; j < 4; j++) av[j] = *(const float4*)(asrc + j * 4);
        cvt_sts16(adst[0],      av[0], av[1]);
        cvt_sts16(adst[0] + 16, av[2], av[3]);
        #pragma unroll
        for (int j = 0; j < 4; j++) av[j] = *(const float4*)(asrc + 16 + j * 4);
        cvt_sts16(adst[0] + 32, av[0], av[1]);
        cvt_sts16(adst[0] + 48, av[2], av[3]);
    }
    asm volatile("cp.async.wait_group 0;" ::: "memory");
    __syncthreads();

    #pragma unroll
    for (int ch = 0; ch < 2; ch++) {
        const int cur = ch;
        float4 av[4];
        if (ch == 0) {
            #pragma unroll
            for (int j = 0; j < 8; j++)
                cp_async16(wdst[1] + j * 16, wsrc + 256 + j * 16);
            asm volatile("cp.async.commit_group;");
            // FIX: chunk 1 of A lives at +128 floats (k = 128..255)
            #pragma unroll
            for (int j = 0; j < 4; j++)
                av[j] = *(const float4*)(asrc + 128 + j * 4);
        }

        // ---- first half of MMAs (ks 0..3) ----
        #pragma unroll
        for (int ks = 0; ks < 4; ks++) {
            uint32_t ah[2][4];
            ldsm_x4(ah[0][0], ah[0][1], ah[0][2], ah[0][3], albase[cur] + ks * 32);
            ldsm_x4(ah[1][0], ah[1][1], ah[1][2], ah[1][3],
                    albase[cur] + 16 * RB2 + ks * 32);
            uint32_t bw[8][2];
            #pragma unroll
            for (int nfp = 0; nfp < 4; nfp++) {
                uint32_t q0, q1, q2, q3;
                ldsm_x4(q0, q1, q2, q3, wlbase[cur] + nfp * 16 * RB2 + ks * 32);
                bw[2*nfp][0]   = q0;  bw[2*nfp][1]   = q2;
                bw[2*nfp+1][0] = q1;  bw[2*nfp+1][1] = q3;
            }
            #pragma unroll
            for (int nf = 0; nf < 8; nf++) {
                mma16816(acc[0][nf], ah[0], bw[nf][0], bw[nf][1]);
                mma16816(acc[1][nf], ah[1], bw[nf][0], bw[nf][1]);
            }
        }

        if (ch == 0) {
            cvt_sts16(adst[1],      av[0], av[1]);
            cvt_sts16(adst[1] + 16, av[2], av[3]);
            // FIX: second 16 floats of chunk-1 quarter at +144
            #pragma unroll
            for (int j = 0; j < 4; j++)
                av[j] = *(const float4*)(asrc + 144 + j * 4);
        }

        // ---- second half of MMAs (ks 4..7) ----
        #pragma unroll
        for (int ks = 4; ks < 8; ks++) {
            uint32_t ah[2][4];
            ldsm_x4(ah[0][0], ah[0][1], ah[0][2], ah[0][3], albase[cur] + ks * 32);
            ldsm_x4(ah[1][0], ah[1][1], ah[1][2], ah[1][3],
                    albase[cur] + 16 * RB2 + ks * 32);
            uint32_t bw[8][2];
            #pragma unroll
            for (int nfp = 0; nfp < 4; nfp++) {
                uint32_t q0, q1, q2, q3;
                ldsm_x4(q0, q1, q2, q3, wlbase[cur] + nfp * 16 * RB2 + ks * 32);
                bw[2*nfp][0]   = q0;  bw[2*nfp][1]   = q2;
                bw[2*nfp+1][0] = q1;  bw[2*nfp+1][1] = q3;
            }
            #pragma unroll
            for (int nf = 0; nf < 8; nf++) {
                mma16816(acc[0][nf], ah[0], bw[nf][0], bw[nf][1]);
                mma16816(acc[1][nf], ah[1], bw[nf][0], bw[nf][1]);
            }
        }

        if (ch == 0) {
            cvt_sts16(adst[1] + 32, av[0], av[1]);
            cvt_sts16(adst[1] + 48, av[2], av[3]);
            asm volatile("cp.async.wait_group 0;" ::: "memory");
            __syncthreads();
        }
    }

    // ---- epilogue: +bias, convert fp16, store ----
    #pragma unroll
    for (int mf = 0; mf < 2; mf++) {
        __half* r0 = Cout + (size_t)(m0 + wm + mf * 16 + g) * 256 + wn;
        __half* r8 = r0 + (size_t)8 * 256;
        #pragma unroll
        for (int nf = 0; nf < 8; nf++) {
            float2 bv = *(const float2*)(b_val + wn + nf * 8 + t2);
            *(__half2*)(r0 + nf * 8 + t2) =
                __floats2half2_rn(acc[mf][nf][0] + bv.x, acc[mf][nf][1] + bv.y);
            *(__half2*)(r8 + nf * 8 + t2) =
                __floats2half2_rn(acc[mf][nf][2] + bv.x, acc[mf][nf][3] + bv.y);
        }
    }
}

// ---------------- out projection: mma fp16 3-product (AhWh + AlWh + AhWl) ----------------
__global__ void __launch_bounds__(256, 2)
out_gemm_mma(const float* __restrict__ A, const float* __restrict__ bias,
             float* __restrict__ Cout)
{
    extern __shared__ char smem[];
    const int tid = threadIdx.x;
    const int wid = tid >> 5, lid = tid & 31;
    const int g   = lid >> 2;
    const int t2  = (lid & 3) * 2;
    const int wm  = (wid & 3) * 32;
    const int wn  = (wid >> 2) * 64;
    const int m0  = blockIdx.x * 128;
    const int n0  = blockIdx.y * 128;

    float acc[2][8][4];
    #pragma unroll
    for (int i = 0; i < 2; i++)
        #pragma unroll
        for (int j = 0; j < 8; j++)
            #pragma unroll
            for (int k = 0; k < 4; k++) acc[i][j][k] = 0.f;

    const int lrow  = tid >> 1;
    const int lhalf = tid & 1;

    for (int ch = 0; ch < 4; ch++) {
        {
            const float4* ap = (const float4*)(A + (size_t)(m0 + lrow) * 256 + ch * 64 + lhalf * 32);
            char* ahb = smem + OSM_AH + lrow * ROWB + lhalf * 64;
            char* alb = smem + OSM_AL + lrow * ROWB + lhalf * 64;
            #pragma unroll
            for (int j = 0; j < 4; j++) {
                float4 v0 = ap[2 * j], v1 = ap[2 * j + 1];
                float f[8] = {v0.x, v0.y, v0.z, v0.w, v1.x, v1.y, v1.z, v1.w};
                unsigned hb[8], lb[8];
                #pragma unroll
                for (int e = 0; e < 8; e++) {
                    __half h = __float2half_rn(f[e]);
                    hb[e] = __half_as_ushort(h);
                    lb[e] = __half_as_ushort(__float2half_rn(f[e] - __half2float(h)));
                }
                *(uint4*)(ahb + j * 16) = make_uint4(hb[0] | (hb[1] << 16), hb[2] | (hb[3] << 16),
                                                    hb[4] | (hb[5] << 16), hb[6] | (hb[7] << 16));
                *(uint4*)(alb + j * 16) = make_uint4(lb[0] | (lb[1] << 16), lb[2] | (lb[3] << 16),
                                                    lb[4] | (lb[5] << 16), lb[6] | (lb[7] << 16));
            }
        }
        {
            const uint4* wh = (const uint4*)((const char*)g_woT_hi + (size_t)(n0 + lrow) * 512 + ch * 128 + lhalf * 64);
            const uint4* wl = (const uint4*)((const char*)g_woT_lo + (size_t)(n0 + lrow) * 512 + ch * 128 + lhalf * 64);
            char* whb = smem + OSM_WH + lrow * ROWB + lhalf * 64;
            char* wlb = smem + OSM_WL + lrow * ROWB + lhalf * 64;
            #pragma unroll
            for (int j = 0; j < 4; j++) {
                *(uint4*)(whb + j * 16) = wh[j];
                *(uint4*)(wlb + j * 16) = wl[j];
            }
        }
        __syncthreads();

        #pragma unroll
        for (int ks = 0; ks < 4; ks++) {
            const int koff = (ks * 16 + t2) * 2;
            uint32_t ah[2][4], al[2][4];
            #pragma unroll
            for (int mf = 0; mf < 2; mf++) {
                const char* pa = smem + (wm + mf * 16 + g) * ROWB + koff;
                ah[mf][0] = *(const uint32_t*)(pa + OSM_AH);
                ah[mf][1] = *(const uint32_t*)(pa + OSM_AH + 8 * ROWB);
                ah[mf][2] = *(const uint32_t*)(pa + OSM_AH + 16);
                ah[mf][3] = *(const uint32_t*)(pa + OSM_AH + 8 * ROWB + 16);
                al[mf][0] = *(const uint32_t*)(pa + OSM_AL);
                al[mf][1] = *(const uint32_t*)(pa + OSM_AL + 8 * ROWB);
                al[mf][2] = *(const uint32_t*)(pa + OSM_AL + 16);
                al[mf][3] = *(const uint32_t*)(pa + OSM_AL + 8 * ROWB + 16);
            }
            #pragma unroll
            for (int nf = 0; nf < 8; nf++) {
                const char* pb = smem + (wn + nf * 8 + g) * ROWB + koff;
                uint32_t bh0 = *(const uint32_t*)(pb + OSM_WH);
                uint32_t bh1 = *(const uint32_t*)(pb + OSM_WH + 16);
                uint32_t bl0 = *(const uint32_t*)(pb + OSM_WL);
                uint32_t bl1 = *(const uint32_t*)(pb + OSM_WL + 16);
                mma16816(acc[0][nf], ah[0], bh0, bh1);
                mma16816(acc[1][nf], ah[1], bh0, bh1);
                mma16816(acc[0][nf], al[0], bh0, bh1);
                mma16816(acc[1][nf], al[1], bh0, bh1);
                mma16816(acc[0][nf], ah[0], bl0, bl1);
                mma16816(acc[1][nf], ah[1], bl0, bl1);
            }
        }
        __syncthreads();
    }

    #pragma unroll
    for (int mf = 0; mf < 2; mf++) {
        float* r0 = Cout + (size_t)(m0 + wm + mf * 16 + g) * 256 + n0 + wn;
        float* r8 = r0 + (size_t)8 * 256;
        #pragma unroll
        for (int nf = 0; nf < 8; nf++) {
            float2 bv = *(const float2*)(bias + n0 + wn + nf * 8 + t2);
            float2 o0, o1;
            o0.x = acc[mf][nf][0] + bv.x;  o0.y = acc[mf][nf][1] + bv.y;
            o1.x = acc[mf][nf][2] + bv.x;  o1.y = acc[mf][nf][3] + bv.y;
            *(float2*)(r0 + nf * 8 + t2) = o0;
            *(float2*)(r8 + nf * 8 + t2) = o1;
        }
    }
}

// ---------------- softmax + deformable sampling (128 thr, half2 channels) ----------------
__global__ void __launch_bounds__(128)
sample_kernel(const float* __restrict__ refp, float* __restrict__ mid)
{
    const int bq  = blockIdx.x;
    const int b   = bq / Q_;
    const int tid = threadIdx.x;
    const int h   = tid >> 4;
    const int c2  = tid & 15;

    __shared__ float s_off[192];
    __shared__ float s_att[96];
    __shared__ float s_r[4];
    __shared__ int   s_idx[96 * 4];
    __shared__ float s_w[96 * 4];

    for (int i = tid; i < 192; i += 128) s_off[i] = g_offs[bq * 192 + i];
    if (tid < 96) s_att[tid] = g_attn[bq * 96 + tid];
    if (tid < 4)  s_r[tid]   = refp[bq * 4 + tid];
    __syncthreads();

    if (tid < 8) {
        float mx = -1e30f;
        #pragma unroll
        for (int p = 0; p < TP_; p++) mx = fmaxf(mx, s_att[tid * TP_ + p]);
        float sm = 0.f;
        #pragma unroll
        for (int p = 0; p < TP_; p++) {
            float e = expf(s_att[tid * TP_ + p] - mx);
            s_att[tid * TP_ + p] = e;
            sm += e;
        }
        float inv = 1.f / sm;
        #pragma unroll
        for (int p = 0; p < TP_; p++) s_att[tid * TP_ + p] *= inv;
    }
    __syncthreads();

    if (tid < 96) {
        const int p = tid % TP_;
        const int l = p >> 2;
        const int Wd = (l == 0) ? 80 : (l == 1) ? 40 : 20;
        const int st = (l == 0) ? 0  : (l == 1) ? 6400 : 8000;
        const float rx = s_r[0], ry = s_r[1];
        const float rw = s_r[2] * 0.125f;
        const float rh = s_r[3] * 0.125f;
        const float a  = s_att[tid];

        const float gx = (rx + s_off[tid * 2 + 0] * rw) * (float)Wd - 0.5f;
        const float gy = (ry + s_off[tid * 2 + 1] * rh) * (float)Wd - 0.5f;
        const float x0f = floorf(gx), y0f = floorf(gy);
        const float fx = gx - x0f, fy = gy - y0f;
        const int ix0 = (int)x0f, iy0 = (int)y0f;
        const int ix1 = ix0 + 1,  iy1 = iy0 + 1;
        const bool vx0 = (ix0 >= 0) & (ix0 < Wd);
        const bool vx1 = (ix1 >= 0) & (ix1 < Wd);
        const bool vy0 = (iy0 >= 0) & (iy0 < Wd);
        const bool vy1 = (iy1 >= 0) & (iy1 < Wd);
        const int ix0c = min(max(ix0, 0), Wd - 1);
        const int ix1c = min(max(ix1, 0), Wd - 1);
        const int iy0c = min(max(iy0, 0), Wd - 1);
        const int iy1c = min(max(iy1, 0), Wd - 1);

        s_w[tid * 4 + 0] = (vx0 & vy0) ? (1.f - fx) * (1.f - fy) * a : 0.f;
        s_w[tid * 4 + 1] = (vx1 & vy0) ? fx * (1.f - fy) * a : 0.f;
        s_w[tid * 4 + 2] = (vx0 & vy1) ? (1.f - fx) * fy * a : 0.f;
        s_w[tid * 4 + 3] = (vx1 & vy1) ? fx * fy * a : 0.f;
        s_idx[tid * 4 + 0] = (st + iy0c * Wd + ix0c) * D_;
        s_idx[tid * 4 + 1] = (st + iy0c * Wd + ix1c) * D_;
        s_idx[tid * 4 + 2] = (st + iy1c * Wd + ix0c) * D_;
        s_idx[tid * 4 + 3] = (st + iy1c * Wd + ix1c) * D_;
    }
    __syncthreads();

    const __half* vb = g_value + (size_t)b * S_ * D_ + h * C_ + c2 * 2;

    float accx = 0.f, accy = 0.f;
    #pragma unroll
    for (int p = 0; p < TP_; p++) {
        const int e = (h * TP_ + p) * 4;
        const int   i0 = s_idx[e], i1 = s_idx[e + 1], i2 = s_idx[e + 2], i3 = s_idx[e + 3];
        const float w0 = s_w[e],   w1 = s_w[e + 1],   w2 = s_w[e + 2],   w3 = s_w[e + 3];
        float2 v0 = __half22float2(*(const __half2*)(vb + i0));
        float2 v1 = __half22float2(*(const __half2*)(vb + i1));
        float2 v2 = __half22float2(*(const __half2*)(vb + i2));
        float2 v3 = __half22float2(*(const __half2*)(vb + i3));
        accx = fmaf(w0, v0.x, accx);  accy = fmaf(w0, v0.y, accy);
        accx = fmaf(w1, v1.x, accx);  accy = fmaf(w1, v1.y, accy);
        accx = fmaf(w2, v2.x, accx);  accy = fmaf(w2, v2.y, accy);
        accx = fmaf(w3, v3.x, accx);  accy = fmaf(w3, v3.y, accy);
    }
    *(float2*)(mid + (size_t)bq * D_ + h * C_ + c2 * 2) = make_float2(accx, accy);
}

// ---------------- launcher ----------------
extern "C" void kernel_launch(void* const* d_in, const int* in_sizes, int n_in,
                              void* d_out, int out_size)
{
    (void)in_sizes; (void)n_in; (void)out_size;
    const float* hidden = (const float*)d_in[0];
    const float* enc    = (const float*)d_in[1];
    const float* refp   = (const float*)d_in[2];
    const float* W_off  = (const float*)d_in[3];
    const float* b_off  = (const float*)d_in[4];
    const float* W_attn = (const float*)d_in[5];
    const float* b_attn = (const float*)d_in[6];
    const float* W_val  = (const float*)d_in[7];
    const float* b_val  = (const float*)d_in[8];
    const float* W_out  = (const float*)d_in[9];
    const float* b_out  = (const float*)d_in[10];
    float* out = (float*)d_out;

    __half* p_value;
    float*  p_mid;
    cudaGetSymbolAddress((void**)&p_value, g_value);
    cudaGetSymbolAddress((void**)&p_mid,   g_mid);

    cudaFuncSetAttribute(fused_main,   cudaFuncAttributeMaxDynamicSharedMemorySize, VSM_TOT);
    cudaFuncSetAttribute(out_gemm_mma, cudaFuncAttributeMaxDynamicSharedMemorySize, OSM_TOT);

    // 0) transpose + fp16-convert W_val (z=0) and W_out hi/lo (z=1)
    prep_w_kernel<<<dim3(8, 8, 2), dim3(32, 8)>>>(W_val, W_out);

    // 1) fused: qproj blocks (first 225) + 2-phase value GEMM blocks (2100)
    fused_main<<<NQPROJ + B_ * S_ / 128, 512, VSM_TOT>>>(
        enc, b_val, p_value, hidden, W_off, b_off, W_attn, b_attn);

    // 2) softmax + bilinear gather + weighted sum
    sample_kernel<<<B_ * Q_, 128>>>(refp, p_mid);

    // 3) output projection on tensor cores (3-product)
    out_gemm_mma<<<dim3(B_ * Q_ / 128, 2), 256, OSM_TOT>>>(p_mid, b_out, out);
}

// round 15
// speedup vs baseline: 1.1138x; 1.1005x over previous
#include <cuda_runtime.h>
#include <cuda_fp16.h>
#include <math.h>
#include <stdint.h>

#define B_   32
#define Q_   300
#define D_   256
#define H_   8
#define C_   32
#define S_   8400
#define TP_  12

// ---------------- scratch (no allocations allowed) ----------------
__device__ __half g_value[(long long)B_ * S_ * D_];  // 137 MB (fp16 value)
__device__ float  g_offs [B_ * Q_ * 192];
__device__ float  g_attn [B_ * Q_ * 96];
__device__ float  g_mid  [B_ * Q_ * D_];
__device__ __half g_wT    [D_ * D_];                 // W_val^T fp16
__device__ __half g_woT_hi[D_ * D_];                 // W_out^T fp16 hi
__device__ __half g_woT_lo[D_ * D_];                 // W_out^T fp16 lo

__device__ __forceinline__ uint32_t smem_u32(const void* p) {
    uint32_t a;
    asm("{ .reg .u64 t; cvta.to.shared.u64 t, %1; cvt.u32.u64 %0, t; }" : "=r"(a) : "l"(p));
    return a;
}
__device__ __forceinline__ void cp_async16(uint32_t dst, const void* src) {
    asm volatile("cp.async.cg.shared.global [%0], [%1], 16;" :: "r"(dst), "l"(src));
}
__device__ __forceinline__ void ldsm_x4(uint32_t& r0, uint32_t& r1, uint32_t& r2,
                                        uint32_t& r3, uint32_t addr) {
    asm volatile("ldmatrix.sync.aligned.m8n8.x4.shared.b16 {%0,%1,%2,%3}, [%4];"
        : "=r"(r0), "=r"(r1), "=r"(r2), "=r"(r3) : "r"(addr));
}
__device__ __forceinline__ void cvt_sts16(uint32_t dst, float4 a, float4 b) {
    __half2 p0 = __floats2half2_rn(a.x, a.y);
    __half2 p1 = __floats2half2_rn(a.z, a.w);
    __half2 p2 = __floats2half2_rn(b.x, b.y);
    __half2 p3 = __floats2half2_rn(b.z, b.w);
    asm volatile("st.shared.v4.b32 [%0], {%1,%2,%3,%4};"
        :: "r"(dst), "r"(*(uint32_t*)&p0), "r"(*(uint32_t*)&p1),
           "r"(*(uint32_t*)&p2), "r"(*(uint32_t*)&p3));
}

// ---------------- prep: transpose weights -> fp16 (z=0: W_val, z=1: W_out hi/lo) ----------------
__global__ void prep_w_kernel(const float* __restrict__ Wv, const float* __restrict__ Wo) {
    __shared__ float t[32][33];
    const float* src = blockIdx.z ? Wo : Wv;
    int bx = blockIdx.x, by = blockIdx.y;
    int tx = threadIdx.x, ty = threadIdx.y;   // 32 x 8
    #pragma unroll
    for (int i = 0; i < 32; i += 8)
        t[ty + i][tx] = src[(size_t)(by * 32 + ty + i) * 256 + bx * 32 + tx];
    __syncthreads();
    #pragma unroll
    for (int i = 0; i < 32; i += 8) {
        int n = bx * 32 + ty + i;
        int k = by * 32 + tx;
        float v = t[tx][ty + i];
        __half h = __float2half_rn(v);
        if (blockIdx.z == 0) {
            g_wT[(size_t)n * 256 + k] = h;
        } else {
            g_woT_hi[(size_t)n * 256 + k] = h;
            g_woT_lo[(size_t)n * 256 + k] = __float2half_rn(v - __half2float(h));
        }
    }
}

// ---------------- mma helper ----------------
__device__ __forceinline__ void mma16816(float* c, const uint32_t* a,
                                         uint32_t b0, uint32_t b1) {
    asm volatile(
        "mma.sync.aligned.m16n8k16.row.col.f32.f16.f16.f32 "
        "{%0,%1,%2,%3}, {%4,%5,%6,%7}, {%8,%9}, {%0,%1,%2,%3};"
        : "+f"(c[0]), "+f"(c[1]), "+f"(c[2]), "+f"(c[3])
        : "r"(a[0]), "r"(a[1]), "r"(a[2]), "r"(a[3]), "r"(b0), "r"(b1));
}

#define ROWB 144                 // 64 halves + 8 pad = 144 bytes/row
#define VAB0 0                   // A: 64 rows x 144B = 9216
#define VAB1 9216
#define VWB0 18432               // W: 256 rows x 144B = 36864
#define VWB1 55296
#define VSM_TOT 92160            // 2 CTAs/SM -> 184 KB
#define OSM_AH 0
#define OSM_AL 18432
#define OSM_WH 36864
#define OSM_WL 55296
#define OSM_TOT 73728
#define NQPROJ 225

// ---------------- fused: qproj (fp32 FFMA) + value GEMM (M64xN256, 2 CTA/SM) ----
__global__ void __launch_bounds__(256, 2)
fused_main(const float* __restrict__ enc, const float* __restrict__ b_val,
           __half* __restrict__ Cout,
           const float* __restrict__ hidden,
           const float* __restrict__ W_off, const float* __restrict__ b_off,
           const float* __restrict__ W_attn, const float* __restrict__ b_attn)
{
    extern __shared__ char smem[];
    const int tid = threadIdx.x;

    if (blockIdx.x < NQPROJ) {
        // ================= qproj: (9600,256)@(256,288), 256 threads, 8x8 micro ====
        const int K = 256, M = B_ * Q_, N = 288;
        float (*As)[132] = (float(*)[132])(smem);
        float (*Ws)[128] = (float(*)[128])(smem + 16 * 132 * 4);

        const int tx  = tid & 15;
        const int ty  = tid >> 4;
        const int m0  = (blockIdx.x / 3) * 128;
        const int n0  = (blockIdx.x % 3) * 128;

        float acc[8][8];
        #pragma unroll
        for (int i = 0; i < 8; i++)
            #pragma unroll
            for (int j = 0; j < 8; j++) acc[i][j] = 0.f;

        for (int kt = 0; kt < K; kt += 16) {
            #pragma unroll
            for (int i = 0; i < 2; i++) {
                int idx = tid + i * 256;
                int row = idx >> 2;
                int kq  = (idx & 3) * 4;
                float4 v = make_float4(0.f, 0.f, 0.f, 0.f);
                int gr = m0 + row;
                if (gr < M)
                    v = *(const float4*)(hidden + (size_t)gr * K + kt + kq);
                As[kq + 0][row] = v.x;
                As[kq + 1][row] = v.y;
                As[kq + 2][row] = v.z;
                As[kq + 3][row] = v.w;
            }
            #pragma unroll
            for (int i = 0; i < 2; i++) {
                int idx = tid + i * 256;
                int kr  = idx >> 5;
                int c4  = (idx & 31) * 4;
                float4 v = make_float4(0.f, 0.f, 0.f, 0.f);
                int gc = n0 + c4;
                if (gc < 192)
                    v = *(const float4*)(W_off + (size_t)(kt + kr) * 192 + gc);
                else if (gc < N)
                    v = *(const float4*)(W_attn + (size_t)(kt + kr) * 96 + gc - 192);
                *(float4*)&Ws[kr][c4] = v;
            }
            __syncthreads();

            #pragma unroll
            for (int k = 0; k < 16; k++) {
                float a[8], b[8];
                *(float4*)&a[0] = *(const float4*)&As[k][ty * 8];
                *(float4*)&a[4] = *(const float4*)&As[k][ty * 8 + 4];
                *(float4*)&b[0] = *(const float4*)&Ws[k][tx * 8];
                *(float4*)&b[4] = *(const float4*)&Ws[k][tx * 8 + 4];
                #pragma unroll
                for (int i = 0; i < 8; i++)
                    #pragma unroll
                    for (int j = 0; j < 8; j++)
                        acc[i][j] = fmaf(a[i], b[j], acc[i][j]);
            }
            __syncthreads();
        }

        #pragma unroll
        for (int i = 0; i < 8; i++) {
            int gr = m0 + ty * 8 + i;
            if (gr >= M) continue;
            #pragma unroll
            for (int j = 0; j < 8; j += 4) {
                int gc = n0 + tx * 8 + j;
                if (gc < 192) {
                    float4 o;
                    o.x = acc[i][j + 0] + b_off[gc + 0];
                    o.y = acc[i][j + 1] + b_off[gc + 1];
                    o.z = acc[i][j + 2] + b_off[gc + 2];
                    o.w = acc[i][j + 3] + b_off[gc + 3];
                    *(float4*)(g_offs + (size_t)gr * 192 + gc) = o;
                } else if (gc < N) {
                    int ga = gc - 192;
                    float4 o;
                    o.x = acc[i][j + 0] + b_attn[ga + 0];
                    o.y = acc[i][j + 1] + b_attn[ga + 1];
                    o.z = acc[i][j + 2] + b_attn[ga + 2];
                    o.w = acc[i][j + 3] + b_attn[ga + 3];
                    *(float4*)(g_attn + (size_t)gr * 96 + ga) = o;
                }
            }
        }
        return;
    }

    // ================= value GEMM: 64M x 256N per block, 8 warps, pipelined ======
    const int id  = blockIdx.x - NQPROJ;
    const int wid = tid >> 5, lid = tid & 31;
    const int g   = lid >> 2;
    const int t2  = (lid & 3) * 2;
    const int wm  = (wid & 1) * 32;      // 2 M-warps
    const int wn  = (wid >> 1) * 64;     // 4 N-warps -> 256 cols
    const int m0  = id * 64;

    const uint32_t sb = smem_u32(smem);
    const int arow = tid >> 2, aq = tid & 3;       // A: 64 rows x 4 quarters (16 fl)
    const int wrow = tid;                          // W: 256 rows, 1 per thread (128B/row)

    const float* asrc = enc + (size_t)(m0 + arow) * 256 + aq * 16;
    const char*  wsrc = (const char*)g_wT + (size_t)wrow * 512;
    const uint32_t adst[2] = { sb + VAB0 + (uint32_t)(arow * ROWB + aq * 32),
                               sb + VAB1 + (uint32_t)(arow * ROWB + aq * 32) };
    const uint32_t wdst[2] = { sb + VWB0 + (uint32_t)(wrow * ROWB),
                               sb + VWB1 + (uint32_t)(wrow * ROWB) };

    const uint32_t lmoff = (uint32_t)(((lid & 7) + ((lid >> 3) & 1) * 8) * ROWB
                                      + (lid >> 4) * 16);
    const uint32_t albase[2] = { sb + VAB0 + (uint32_t)(wm * ROWB) + lmoff,
                                 sb + VAB1 + (uint32_t)(wm * ROWB) + lmoff };
    const uint32_t wlbase[2] = { sb + VWB0 + (uint32_t)(wn * ROWB) + lmoff,
                                 sb + VWB1 + (uint32_t)(wn * ROWB) + lmoff };

    float acc[2][8][4];
    #pragma unroll
    for (int i = 0; i < 2; i++)
        #pragma unroll
        for (int j = 0; j < 8; j++)
            #pragma unroll
            for (int k = 0; k < 4; k++) acc[i][j][k] = 0.f;

    // ---- prologue: stage chunk 0 (W: full 128B per row!) ----
    #pragma unroll
    for (int j = 0; j < 8; j++)
        cp_async16(wdst[0] + j * 16, wsrc + j * 16);
    asm volatile("cp.async.commit_group;");
    {
        float4 av[4];
        #pragma unroll
        for (int j = 0; j < 4; j++)
            av[j] = *(const float4*)(asrc + j * 4);
        cvt_sts16(adst[0],      av[0], av[1]);
        cvt_sts16(adst[0] + 16, av[2], av[3]);
    }
    asm volatile("cp.async.wait_group 0;" ::: "memory");
    __syncthreads();

    for (int ch = 0; ch < 4; ch++) {
        const int cur = ch & 1, nxt = cur ^ 1;
        float4 av[4];
        if (ch < 3) {
            // async W prefetch (chunk stride = 128 BYTES) + A prefetch into regs
            #pragma unroll
            for (int j = 0; j < 8; j++)
                cp_async16(wdst[nxt] + j * 16, wsrc + (ch + 1) * 128 + j * 16);
            asm volatile("cp.async.commit_group;");
            #pragma unroll
            for (int j = 0; j < 4; j++)
                av[j] = *(const float4*)(asrc + (ch + 1) * 64 + j * 4);
        }

        // ---- MMA on current buffers via ldmatrix (hides prefetch latency) ----
        #pragma unroll
        for (int ks = 0; ks < 4; ks++) {
            uint32_t ah[2][4];
            ldsm_x4(ah[0][0], ah[0][1], ah[0][2], ah[0][3], albase[cur] + ks * 32);
            ldsm_x4(ah[1][0], ah[1][1], ah[1][2], ah[1][3],
                    albase[cur] + 16 * ROWB + ks * 32);
            uint32_t bw[8][2];
            #pragma unroll
            for (int nfp = 0; nfp < 4; nfp++) {
                uint32_t q0, q1, q2, q3;
                ldsm_x4(q0, q1, q2, q3, wlbase[cur] + nfp * 16 * ROWB + ks * 32);
                bw[2*nfp][0]   = q0;  bw[2*nfp][1]   = q2;
                bw[2*nfp+1][0] = q1;  bw[2*nfp+1][1] = q3;
            }
            #pragma unroll
            for (int nf = 0; nf < 8; nf++) {
                mma16816(acc[0][nf], ah[0], bw[nf][0], bw[nf][1]);
                mma16816(acc[1][nf], ah[1], bw[nf][0], bw[nf][1]);
            }
        }

        if (ch < 3) {
            cvt_sts16(adst[nxt],      av[0], av[1]);
            cvt_sts16(adst[nxt] + 16, av[2], av[3]);
            asm volatile("cp.async.wait_group 0;" ::: "memory");
        }
        __syncthreads();
    }

    // ---- epilogue: +bias, convert fp16, store ----
    #pragma unroll
    for (int mf = 0; mf < 2; mf++) {
        __half* r0 = Cout + (size_t)(m0 + wm + mf * 16 + g) * 256 + wn;
        __half* r8 = r0 + (size_t)8 * 256;
        #pragma unroll
        for (int nf = 0; nf < 8; nf++) {
            float2 bv = *(const float2*)(b_val + wn + nf * 8 + t2);
            *(__half2*)(r0 + nf * 8 + t2) =
                __floats2half2_rn(acc[mf][nf][0] + bv.x, acc[mf][nf][1] + bv.y);
            *(__half2*)(r8 + nf * 8 + t2) =
                __floats2half2_rn(acc[mf][nf][2] + bv.x, acc[mf][nf][3] + bv.y);
        }
    }
}

// ---------------- out projection: mma fp16 3-product (AhWh + AlWh + AhWl) ----------------
__global__ void __launch_bounds__(256, 2)
out_gemm_mma(const float* __restrict__ A, const float* __restrict__ bias,
             float* __restrict__ Cout)
{
    extern __shared__ char smem[];
    const int tid = threadIdx.x;
    const int wid = tid >> 5, lid = tid & 31;
    const int g   = lid >> 2;
    const int t2  = (lid & 3) * 2;
    const int wm  = (wid & 3) * 32;
    const int wn  = (wid >> 2) * 64;
    const int m0  = blockIdx.x * 128;
    const int n0  = blockIdx.y * 128;

    float acc[2][8][4];
    #pragma unroll
    for (int i = 0; i < 2; i++)
        #pragma unroll
        for (int j = 0; j < 8; j++)
            #pragma unroll
            for (int k = 0; k < 4; k++) acc[i][j][k] = 0.f;

    const int lrow  = tid >> 1;
    const int lhalf = tid & 1;

    for (int ch = 0; ch < 4; ch++) {
        {
            const float4* ap = (const float4*)(A + (size_t)(m0 + lrow) * 256 + ch * 64 + lhalf * 32);
            char* ahb = smem + OSM_AH + lrow * ROWB + lhalf * 64;
            char* alb = smem + OSM_AL + lrow * ROWB + lhalf * 64;
            #pragma unroll
            for (int j = 0; j < 4; j++) {
                float4 v0 = ap[2 * j], v1 = ap[2 * j + 1];
                float f[8] = {v0.x, v0.y, v0.z, v0.w, v1.x, v1.y, v1.z, v1.w};
                unsigned hb[8], lb[8];
                #pragma unroll
                for (int e = 0; e < 8; e++) {
                    __half h = __float2half_rn(f[e]);
                    hb[e] = __half_as_ushort(h);
                    lb[e] = __half_as_ushort(__float2half_rn(f[e] - __half2float(h)));
                }
                *(uint4*)(ahb + j * 16) = make_uint4(hb[0] | (hb[1] << 16), hb[2] | (hb[3] << 16),
                                                    hb[4] | (hb[5] << 16), hb[6] | (hb[7] << 16));
                *(uint4*)(alb + j * 16) = make_uint4(lb[0] | (lb[1] << 16), lb[2] | (lb[3] << 16),
                                                    lb[4] | (lb[5] << 16), lb[6] | (lb[7] << 16));
            }
        }
        {
            const uint4* wh = (const uint4*)((const char*)g_woT_hi + (size_t)(n0 + lrow) * 512 + ch * 128 + lhalf * 64);
            const uint4* wl = (const uint4*)((const char*)g_woT_lo + (size_t)(n0 + lrow) * 512 + ch * 128 + lhalf * 64);
            char* whb = smem + OSM_WH + lrow * ROWB + lhalf * 64;
            char* wlb = smem + OSM_WL + lrow * ROWB + lhalf * 64;
            #pragma unroll
            for (int j = 0; j < 4; j++) {
                *(uint4*)(whb + j * 16) = wh[j];
                *(uint4*)(wlb + j * 16) = wl[j];
            }
        }
        __syncthreads();

        #pragma unroll
        for (int ks = 0; ks < 4; ks++) {
            const int koff = (ks * 16 + t2) * 2;
            uint32_t ah[2][4], al[2][4];
            #pragma unroll
            for (int mf = 0; mf < 2; mf++) {
                const char* pa = smem + (wm + mf * 16 + g) * ROWB + koff;
                ah[mf][0] = *(const uint32_t*)(pa + OSM_AH);
                ah[mf][1] = *(const uint32_t*)(pa + OSM_AH + 8 * ROWB);
                ah[mf][2] = *(const uint32_t*)(pa + OSM_AH + 16);
                ah[mf][3] = *(const uint32_t*)(pa + OSM_AH + 8 * ROWB + 16);
                al[mf][0] = *(const uint32_t*)(pa + OSM_AL);
                al[mf][1] = *(const uint32_t*)(pa + OSM_AL + 8 * ROWB);
                al[mf][2] = *(const uint32_t*)(pa + OSM_AL + 16);
                al[mf][3] = *(const uint32_t*)(pa + OSM_AL + 8 * ROWB + 16);
            }
            #pragma unroll
            for (int nf = 0; nf < 8; nf++) {
                const char* pb = smem + (wn + nf * 8 + g) * ROWB + koff;
                uint32_t bh0 = *(const uint32_t*)(pb + OSM_WH);
                uint32_t bh1 = *(const uint32_t*)(pb + OSM_WH + 16);
                uint32_t bl0 = *(const uint32_t*)(pb + OSM_WL);
                uint32_t bl1 = *(const uint32_t*)(pb + OSM_WL + 16);
                mma16816(acc[0][nf], ah[0], bh0, bh1);
                mma16816(acc[1][nf], ah[1], bh0, bh1);
                mma16816(acc[0][nf], al[0], bh0, bh1);
                mma16816(acc[1][nf], al[1], bh0, bh1);
                mma16816(acc[0][nf], ah[0], bl0, bl1);
                mma16816(acc[1][nf], ah[1], bl0, bl1);
            }
        }
        __syncthreads();
    }

    #pragma unroll
    for (int mf = 0; mf < 2; mf++) {
        float* r0 = Cout + (size_t)(m0 + wm + mf * 16 + g) * 256 + n0 + wn;
        float* r8 = r0 + (size_t)8 * 256;
        #pragma unroll
        for (int nf = 0; nf < 8; nf++) {
            float2 bv = *(const float2*)(bias + n0 + wn + nf * 8 + t2);
            float2 o0, o1;
            o0.x = acc[mf][nf][0] + bv.x;  o0.y = acc[mf][nf][1] + bv.y;
            o1.x = acc[mf][nf][2] + bv.x;  o1.y = acc[mf][nf][3] + bv.y;
            *(float2*)(r0 + nf * 8 + t2) = o0;
            *(float2*)(r8 + nf * 8 + t2) = o1;
        }
    }
}

// ---------------- softmax + deformable sampling (128 thr, half2 channels) ----------------
__global__ void __launch_bounds__(128)
sample_kernel(const float* __restrict__ refp, float* __restrict__ mid)
{
    const int bq  = blockIdx.x;
    const int b   = bq / Q_;
    const int tid = threadIdx.x;
    const int h   = tid >> 4;
    const int c2  = tid & 15;

    __shared__ float s_off[192];
    __shared__ float s_att[96];
    __shared__ float s_r[4];
    __shared__ int   s_idx[96 * 4];
    __shared__ float s_w[96 * 4];

    for (int i = tid; i < 192; i += 128) s_off[i] = g_offs[bq * 192 + i];
    if (tid < 96) s_att[tid] = g_attn[bq * 96 + tid];
    if (tid < 4)  s_r[tid]   = refp[bq * 4 + tid];
    __syncthreads();

    if (tid < 8) {
        float mx = -1e30f;
        #pragma unroll
        for (int p = 0; p < TP_; p++) mx = fmaxf(mx, s_att[tid * TP_ + p]);
        float sm = 0.f;
        #pragma unroll
        for (int p = 0; p < TP_; p++) {
            float e = expf(s_att[tid * TP_ + p] - mx);
            s_att[tid * TP_ + p] = e;
            sm += e;
        }
        float inv = 1.f / sm;
        #pragma unroll
        for (int p = 0; p < TP_; p++) s_att[tid * TP_ + p] *= inv;
    }
    __syncthreads();

    if (tid < 96) {
        const int p = tid % TP_;
        const int l = p >> 2;
        const int Wd = (l == 0) ? 80 : (l == 1) ? 40 : 20;
        const int st = (l == 0) ? 0  : (l == 1) ? 6400 : 8000;
        const float rx = s_r[0], ry = s_r[1];
        const float rw = s_r[2] * 0.125f;
        const float rh = s_r[3] * 0.125f;
        const float a  = s_att[tid];

        const float gx = (rx + s_off[tid * 2 + 0] * rw) * (float)Wd - 0.5f;
        const float gy = (ry + s_off[tid * 2 + 1] * rh) * (float)Wd - 0.5f;
        const float x0f = floorf(gx), y0f = floorf(gy);
        const float fx = gx - x0f, fy = gy - y0f;
        const int ix0 = (int)x0f, iy0 = (int)y0f;
        const int ix1 = ix0 + 1,  iy1 = iy0 + 1;
        const bool vx0 = (ix0 >= 0) & (ix0 < Wd);
        const bool vx1 = (ix1 >= 0) & (ix1 < Wd);
        const bool vy0 = (iy0 >= 0) & (iy0 < Wd);
        const bool vy1 = (iy1 >= 0) & (iy1 < Wd);
        const int ix0c = min(max(ix0, 0), Wd - 1);
        const int ix1c = min(max(ix1, 0), Wd - 1);
        const int iy0c = min(max(iy0, 0), Wd - 1);
        const int iy1c = min(max(iy1, 0), Wd - 1);

        s_w[tid * 4 + 0] = (vx0 & vy0) ? (1.f - fx) * (1.f - fy) * a : 0.f;
        s_w[tid * 4 + 1] = (vx1 & vy0) ? fx * (1.f - fy) * a : 0.f;
        s_w[tid * 4 + 2] = (vx0 & vy1) ? (1.f - fx) * fy * a : 0.f;
        s_w[tid * 4 + 3] = (vx1 & vy1) ? fx * fy * a : 0.f;
        s_idx[tid * 4 + 0] = (st + iy0c * Wd + ix0c) * D_;
        s_idx[tid * 4 + 1] = (st + iy0c * Wd + ix1c) * D_;
        s_idx[tid * 4 + 2] = (st + iy1c * Wd + ix0c) * D_;
        s_idx[tid * 4 + 3] = (st + iy1c * Wd + ix1c) * D_;
    }
    __syncthreads();

    const __half* vb = g_value + (size_t)b * S_ * D_ + h * C_ + c2 * 2;

    float accx = 0.f, accy = 0.f;
    #pragma unroll
    for (int p = 0; p < TP_; p++) {
        const int e = (h * TP_ + p) * 4;
        const int   i0 = s_idx[e], i1 = s_idx[e + 1], i2 = s_idx[e + 2], i3 = s_idx[e + 3];
        const float w0 = s_w[e],   w1 = s_w[e + 1],   w2 = s_w[e + 2],   w3 = s_w[e + 3];
        float2 v0 = __half22float2(*(const __half2*)(vb + i0));
        float2 v1 = __half22float2(*(const __half2*)(vb + i1));
        float2 v2 = __half22float2(*(const __half2*)(vb + i2));
        float2 v3 = __half22float2(*(const __half2*)(vb + i3));
        accx = fmaf(w0, v0.x, accx);  accy = fmaf(w0, v0.y, accy);
        accx = fmaf(w1, v1.x, accx);  accy = fmaf(w1, v1.y, accy);
        accx = fmaf(w2, v2.x, accx);  accy = fmaf(w2, v2.y, accy);
        accx = fmaf(w3, v3.x, accx);  accy = fmaf(w3, v3.y, accy);
    }
    *(float2*)(mid + (size_t)bq * D_ + h * C_ + c2 * 2) = make_float2(accx, accy);
}

// ---------------- launcher ----------------
extern "C" void kernel_launch(void* const* d_in, const int* in_sizes, int n_in,
                              void* d_out, int out_size)
{
    (void)in_sizes; (void)n_in; (void)out_size;
    const float* hidden = (const float*)d_in[0];
    const float* enc    = (const float*)d_in[1];
    const float* refp   = (const float*)d_in[2];
    const float* W_off  = (const float*)d_in[3];
    const float* b_off  = (const float*)d_in[4];
    const float* W_attn = (const float*)d_in[5];
    const float* b_attn = (const float*)d_in[6];
    const float* W_val  = (const float*)d_in[7];
    const float* b_val  = (const float*)d_in[8];
    const float* W_out  = (const float*)d_in[9];
    const float* b_out  = (const float*)d_in[10];
    float* out = (float*)d_out;

    __half* p_value;
    float*  p_mid;
    cudaGetSymbolAddress((void**)&p_value, g_value);
    cudaGetSymbolAddress((void**)&p_mid,   g_mid);

    cudaFuncSetAttribute(fused_main,   cudaFuncAttributeMaxDynamicSharedMemorySize, VSM_TOT);
    cudaFuncSetAttribute(out_gemm_mma, cudaFuncAttributeMaxDynamicSharedMemorySize, OSM_TOT);

    // 0) transpose + fp16-convert W_val (z=0) and W_out hi/lo (z=1)
    prep_w_kernel<<<dim3(8, 8, 2), dim3(32, 8)>>>(W_val, W_out);

    // 1) fused: qproj blocks (first 225) + value GEMM blocks (4200, M64xN256)
    fused_main<<<NQPROJ + B_ * S_ / 64, 256, VSM_TOT>>>(
        enc, b_val, p_value, hidden, W_off, b_off, W_attn, b_attn);

    // 2) softmax + bilinear gather + weighted sum
    sample_kernel<<<B_ * Q_, 128>>>(refp, p_mid);

    // 3) output projection on tensor cores (3-product)
    out_gemm_mma<<<dim3(B_ * Q_ / 128, 2), 256, OSM_TOT>>>(p_mid, b_out, out);
}

// round 16
// speedup vs baseline: 1.3640x; 1.2246x over previous
#include <cuda_runtime.h>
#include <cuda_fp16.h>
#include <math.h>
#include <stdint.h>

#define B_   32
#define Q_   300
#define D_   256
#define H_   8
#define C_   32
#define S_   8400
#define TP_  12

// ---------------- scratch (no allocations allowed) ----------------
__device__ __half g_value[(long long)B_ * S_ * D_];  // 137 MB (fp16 value)
__device__ float  g_offs [B_ * Q_ * 192];
__device__ float  g_attn [B_ * Q_ * 96];
__device__ float  g_mid  [B_ * Q_ * D_];
__device__ __half g_wT    [D_ * D_];                 // W_val^T fp16
__device__ __half g_woT   [D_ * D_];                 // W_out^T fp16

__device__ __forceinline__ uint32_t smem_u32(const void* p) {
    uint32_t a;
    asm("{ .reg .u64 t; cvta.to.shared.u64 t, %1; cvt.u32.u64 %0, t; }" : "=r"(a) : "l"(p));
    return a;
}
__device__ __forceinline__ void cp_async16(uint32_t dst, const void* src) {
    asm volatile("cp.async.cg.shared.global [%0], [%1], 16;" :: "r"(dst), "l"(src));
}
__device__ __forceinline__ void ldsm_x4(uint32_t& r0, uint32_t& r1, uint32_t& r2,
                                        uint32_t& r3, uint32_t addr) {
    asm volatile("ldmatrix.sync.aligned.m8n8.x4.shared.b16 {%0,%1,%2,%3}, [%4];"
        : "=r"(r0), "=r"(r1), "=r"(r2), "=r"(r3) : "r"(addr));
}

// ---------------- prep: transpose weights -> fp16 (z=0: W_val, z=1: W_out) ----------------
__global__ void prep_w_kernel(const float* __restrict__ Wv, const float* __restrict__ Wo) {
    __shared__ float t[32][33];
    const float* src = blockIdx.z ? Wo : Wv;
    int bx = blockIdx.x, by = blockIdx.y;
    int tx = threadIdx.x, ty = threadIdx.y;   // 32 x 8
    #pragma unroll
    for (int i = 0; i < 32; i += 8)
        t[ty + i][tx] = src[(size_t)(by * 32 + ty + i) * 256 + bx * 32 + tx];
    __syncthreads();
    #pragma unroll
    for (int i = 0; i < 32; i += 8) {
        int n = bx * 32 + ty + i;
        int k = by * 32 + tx;
        float v = t[tx][ty + i];
        __half h = __float2half_rn(v);
        if (blockIdx.z == 0) g_wT [(size_t)n * 256 + k] = h;
        else                 g_woT[(size_t)n * 256 + k] = h;
    }
}

// ---------------- mma helper ----------------
__device__ __forceinline__ void mma16816(float* c, const uint32_t* a,
                                         uint32_t b0, uint32_t b1) {
    asm volatile(
        "mma.sync.aligned.m16n8k16.row.col.f32.f16.f16.f32 "
        "{%0,%1,%2,%3}, {%4,%5,%6,%7}, {%8,%9}, {%0,%1,%2,%3};"
        : "+f"(c[0]), "+f"(c[1]), "+f"(c[2]), "+f"(c[3])
        : "r"(a[0]), "r"(a[1]), "r"(a[2]), "r"(a[3]), "r"(b0), "r"(b1));
}

#define ROWB 144                 // 64 halves + 8 pad
#define ABUF0 0
#define ABUF1 18432
#define WBUF0 36864
#define WBUF1 73728
#define VSM_TOT 110592           // fused kernel: 2xA + 2xW ping-pong
#define OSM_AH 0
#define OSM_AL 18432
#define OSM_WH 36864
#define OSM_TOT 55296            // out-proj: AH + AL + WH (2-product)
#define NQPROJ 225

// ---------------- fused: qproj (fp32 FFMA) + pipelined value GEMM (R10 config) ----
__global__ void __launch_bounds__(512, 1)
fused_main(const float* __restrict__ enc, const float* __restrict__ b_val,
           __half* __restrict__ Cout,
           const float* __restrict__ hidden,
           const float* __restrict__ W_off, const float* __restrict__ b_off,
           const float* __restrict__ W_attn, const float* __restrict__ b_attn)
{
    extern __shared__ char smem[];
    const int tid = threadIdx.x;

    if (blockIdx.x < NQPROJ) {
        // ================= qproj: (9600,256)@(256,288), 512 threads, 8x4 micro ====
        const int K = 256, M = B_ * Q_, N = 288;
        float (*As)[132] = (float(*)[132])(smem);
        float (*Ws)[128] = (float(*)[128])(smem + 16 * 132 * 4);

        const int tx  = tid & 31;
        const int ty  = tid >> 5;
        const int m0  = (blockIdx.x / 3) * 128;
        const int n0  = (blockIdx.x % 3) * 128;

        float acc[8][4];
        #pragma unroll
        for (int i = 0; i < 8; i++)
            #pragma unroll
            for (int j = 0; j < 4; j++) acc[i][j] = 0.f;

        for (int kt = 0; kt < K; kt += 16) {
            {
                int row = tid >> 2;
                int kq  = (tid & 3) * 4;
                float4 v = make_float4(0.f, 0.f, 0.f, 0.f);
                int gr = m0 + row;
                if (gr < M)
                    v = *(const float4*)(hidden + (size_t)gr * K + kt + kq);
                As[kq + 0][row] = v.x;
                As[kq + 1][row] = v.y;
                As[kq + 2][row] = v.z;
                As[kq + 3][row] = v.w;
            }
            {
                int kr  = tid >> 5;
                int c4  = (tid & 31) * 4;
                float4 v = make_float4(0.f, 0.f, 0.f, 0.f);
                int gc = n0 + c4;
                if (gc < 192)
                    v = *(const float4*)(W_off + (size_t)(kt + kr) * 192 + gc);
                else if (gc < N)
                    v = *(const float4*)(W_attn + (size_t)(kt + kr) * 96 + gc - 192);
                *(float4*)&Ws[kr][c4] = v;
            }
            __syncthreads();

            #pragma unroll
            for (int k = 0; k < 16; k++) {
                float a[8], b[4];
                *(float4*)&a[0] = *(const float4*)&As[k][ty * 8];
                *(float4*)&a[4] = *(const float4*)&As[k][ty * 8 + 4];
                *(float4*)&b[0] = *(const float4*)&Ws[k][tx * 4];
                #pragma unroll
                for (int i = 0; i < 8; i++)
                    #pragma unroll
                    for (int j = 0; j < 4; j++)
                        acc[i][j] = fmaf(a[i], b[j], acc[i][j]);
            }
            __syncthreads();
        }

        #pragma unroll
        for (int i = 0; i < 8; i++) {
            int gr = m0 + ty * 8 + i;
            if (gr >= M) continue;
            int gc = n0 + tx * 4;
            if (gc < 192) {
                float4 o;
                o.x = acc[i][0] + b_off[gc + 0];
                o.y = acc[i][1] + b_off[gc + 1];
                o.z = acc[i][2] + b_off[gc + 2];
                o.w = acc[i][3] + b_off[gc + 3];
                *(float4*)(g_offs + (size_t)gr * 192 + gc) = o;
            } else if (gc < N) {
                int ga = gc - 192;
                float4 o;
                o.x = acc[i][0] + b_attn[ga + 0];
                o.y = acc[i][1] + b_attn[ga + 1];
                o.z = acc[i][2] + b_attn[ga + 2];
                o.w = acc[i][3] + b_attn[ga + 3];
                *(float4*)(g_attn + (size_t)gr * 96 + ga) = o;
            }
        }
        return;
    }

    // ================= value GEMM: 128M x 256N, pipelined, ldmatrix (R10) =========
    const int id  = blockIdx.x - NQPROJ;
    const int wid = tid >> 5, lid = tid & 31;
    const int g   = lid >> 2;
    const int t2  = (lid & 3) * 2;
    const int wm  = (wid & 3) * 32;
    const int wn  = (wid >> 2) * 64;
    const int m0  = id * 128;

    const uint32_t sb = smem_u32(smem);
    const int arow = tid >> 2, aq = tid & 3;
    const int wrow = tid >> 1, whlf = tid & 1;

    const float* asrc = enc + (size_t)(m0 + arow) * 256 + aq * 16;
    const char*  wsrc = (const char*)g_wT + (size_t)wrow * 512 + whlf * 64;
    const uint32_t adst[2] = { sb + ABUF0 + (uint32_t)(arow * ROWB + aq * 32),
                               sb + ABUF1 + (uint32_t)(arow * ROWB + aq * 32) };
    const uint32_t wdst[2] = { sb + WBUF0 + (uint32_t)(wrow * ROWB + whlf * 64),
                               sb + WBUF1 + (uint32_t)(wrow * ROWB + whlf * 64) };

    const uint32_t lmoff = (uint32_t)(((lid & 7) + ((lid >> 3) & 1) * 8) * ROWB
                                      + (lid >> 4) * 16);
    const uint32_t albase[2] = { sb + ABUF0 + (uint32_t)(wm * ROWB) + lmoff,
                                 sb + ABUF1 + (uint32_t)(wm * ROWB) + lmoff };
    const uint32_t wlbase[2] = { sb + WBUF0 + (uint32_t)(wn * ROWB) + lmoff,
                                 sb + WBUF1 + (uint32_t)(wn * ROWB) + lmoff };

    float acc[2][8][4];
    #pragma unroll
    for (int i = 0; i < 2; i++)
        #pragma unroll
        for (int j = 0; j < 8; j++)
            #pragma unroll
            for (int k = 0; k < 4; k++) acc[i][j][k] = 0.f;

    // ---- prologue: chunk 0 ----
    #pragma unroll
    for (int j = 0; j < 4; j++)
        cp_async16(wdst[0] + j * 16, wsrc + j * 16);
    asm volatile("cp.async.commit_group;");
    {
        float4 av[4];
        #pragma unroll
        for (int j = 0; j < 4; j++)
            av[j] = *(const float4*)(asrc + j * 4);
        #pragma unroll
        for (int j = 0; j < 2; j++) {
            __half2 p0 = __floats2half2_rn(av[2*j].x, av[2*j].y);
            __half2 p1 = __floats2half2_rn(av[2*j].z, av[2*j].w);
            __half2 p2 = __floats2half2_rn(av[2*j+1].x, av[2*j+1].y);
            __half2 p3 = __floats2half2_rn(av[2*j+1].z, av[2*j+1].w);
            uint4 pk = make_uint4(*(uint32_t*)&p0, *(uint32_t*)&p1,
                                  *(uint32_t*)&p2, *(uint32_t*)&p3);
            asm volatile("st.shared.v4.b32 [%0], {%1,%2,%3,%4};"
                :: "r"(adst[0] + j * 16), "r"(pk.x), "r"(pk.y), "r"(pk.z), "r"(pk.w));
        }
    }
    asm volatile("cp.async.wait_group 0;" ::: "memory");
    __syncthreads();

    for (int ch = 0; ch < 4; ch++) {
        const int cur = ch & 1, nxt = cur ^ 1;
        float4 av[4];
        if (ch < 3) {
            #pragma unroll
            for (int j = 0; j < 4; j++)
                cp_async16(wdst[nxt] + j * 16, wsrc + (ch + 1) * 128 + j * 16);
            asm volatile("cp.async.commit_group;");
            #pragma unroll
            for (int j = 0; j < 4; j++)
                av[j] = *(const float4*)(asrc + (ch + 1) * 64 + j * 4);
        }

        // ---- MMA on current buffers via ldmatrix ----
        #pragma unroll
        for (int ks = 0; ks < 4; ks++) {
            uint32_t ah[2][4];
            ldsm_x4(ah[0][0], ah[0][1], ah[0][2], ah[0][3], albase[cur] + ks * 32);
            ldsm_x4(ah[1][0], ah[1][1], ah[1][2], ah[1][3],
                    albase[cur] + 16 * ROWB + ks * 32);
            uint32_t bw[8][2];
            #pragma unroll
            for (int nfp = 0; nfp < 4; nfp++) {
                uint32_t q0, q1, q2, q3;
                ldsm_x4(q0, q1, q2, q3, wlbase[cur] + nfp * 16 * ROWB + ks * 32);
                bw[2*nfp][0]   = q0;  bw[2*nfp][1]   = q2;
                bw[2*nfp+1][0] = q1;  bw[2*nfp+1][1] = q3;
            }
            #pragma unroll
            for (int nf = 0; nf < 8; nf++) {
                mma16816(acc[0][nf], ah[0], bw[nf][0], bw[nf][1]);
                mma16816(acc[1][nf], ah[1], bw[nf][0], bw[nf][1]);
            }
        }

        if (ch < 3) {
            #pragma unroll
            for (int j = 0; j < 2; j++) {
                __half2 p0 = __floats2half2_rn(av[2*j].x, av[2*j].y);
                __half2 p1 = __floats2half2_rn(av[2*j].z, av[2*j].w);
                __half2 p2 = __floats2half2_rn(av[2*j+1].x, av[2*j+1].y);
                __half2 p3 = __floats2half2_rn(av[2*j+1].z, av[2*j+1].w);
                uint4 pk = make_uint4(*(uint32_t*)&p0, *(uint32_t*)&p1,
                                      *(uint32_t*)&p2, *(uint32_t*)&p3);
                asm volatile("st.shared.v4.b32 [%0], {%1,%2,%3,%4};"
                    :: "r"(adst[nxt] + j * 16), "r"(pk.x), "r"(pk.y), "r"(pk.z), "r"(pk.w));
            }
            asm volatile("cp.async.wait_group 0;" ::: "memory");
        }
        __syncthreads();
    }

    // ---- epilogue: +bias, convert fp16, store ----
    #pragma unroll
    for (int mf = 0; mf < 2; mf++) {
        __half* r0 = Cout + (size_t)(m0 + wm + mf * 16 + g) * 256 + wn;
        __half* r8 = r0 + (size_t)8 * 256;
        #pragma unroll
        for (int nf = 0; nf < 8; nf++) {
            float2 bv = *(const float2*)(b_val + wn + nf * 8 + t2);
            *(__half2*)(r0 + nf * 8 + t2) =
                __floats2half2_rn(acc[mf][nf][0] + bv.x, acc[mf][nf][1] + bv.y);
            *(__half2*)(r8 + nf * 8 + t2) =
                __floats2half2_rn(acc[mf][nf][2] + bv.x, acc[mf][nf][3] + bv.y);
        }
    }
}

// ---------------- out projection: mma fp16 2-product ((Ah+Al)·Wh) ----------------
__global__ void __launch_bounds__(256, 2)
out_gemm_mma(const float* __restrict__ A, const float* __restrict__ bias,
             float* __restrict__ Cout)
{
    extern __shared__ char smem[];
    const int tid = threadIdx.x;
    const int wid = tid >> 5, lid = tid & 31;
    const int g   = lid >> 2;
    const int t2  = (lid & 3) * 2;
    const int wm  = (wid & 3) * 32;
    const int wn  = (wid >> 2) * 64;
    const int m0  = blockIdx.x * 128;
    const int n0  = blockIdx.y * 128;

    float acc[2][8][4];
    #pragma unroll
    for (int i = 0; i < 2; i++)
        #pragma unroll
        for (int j = 0; j < 8; j++)
            #pragma unroll
            for (int k = 0; k < 4; k++) acc[i][j][k] = 0.f;

    const int lrow  = tid >> 1;
    const int lhalf = tid & 1;

    for (int ch = 0; ch < 4; ch++) {
        {
            const float4* ap = (const float4*)(A + (size_t)(m0 + lrow) * 256 + ch * 64 + lhalf * 32);
            char* ahb = smem + OSM_AH + lrow * ROWB + lhalf * 64;
            char* alb = smem + OSM_AL + lrow * ROWB + lhalf * 64;
            #pragma unroll
            for (int j = 0; j < 4; j++) {
                float4 v0 = ap[2 * j], v1 = ap[2 * j + 1];
                float f[8] = {v0.x, v0.y, v0.z, v0.w, v1.x, v1.y, v1.z, v1.w};
                unsigned hb[8], lb[8];
                #pragma unroll
                for (int e = 0; e < 8; e++) {
                    __half h = __float2half_rn(f[e]);
                    hb[e] = __half_as_ushort(h);
                    lb[e] = __half_as_ushort(__float2half_rn(f[e] - __half2float(h)));
                }
                *(uint4*)(ahb + j * 16) = make_uint4(hb[0] | (hb[1] << 16), hb[2] | (hb[3] << 16),
                                                    hb[4] | (hb[5] << 16), hb[6] | (hb[7] << 16));
                *(uint4*)(alb + j * 16) = make_uint4(lb[0] | (lb[1] << 16), lb[2] | (lb[3] << 16),
                                                    lb[4] | (lb[5] << 16), lb[6] | (lb[7] << 16));
            }
        }
        {
            const uint4* wh = (const uint4*)((const char*)g_woT + (size_t)(n0 + lrow) * 512 + ch * 128 + lhalf * 64);
            char* whb = smem + OSM_WH + lrow * ROWB + lhalf * 64;
            #pragma unroll
            for (int j = 0; j < 4; j++)
                *(uint4*)(whb + j * 16) = wh[j];
        }
        __syncthreads();

        #pragma unroll
        for (int ks = 0; ks < 4; ks++) {
            const int koff = (ks * 16 + t2) * 2;
            uint32_t ah[2][4], al[2][4];
            #pragma unroll
            for (int mf = 0; mf < 2; mf++) {
                const char* pa = smem + (wm + mf * 16 + g) * ROWB + koff;
                ah[mf][0] = *(const uint32_t*)(pa + OSM_AH);
                ah[mf][1] = *(const uint32_t*)(pa + OSM_AH + 8 * ROWB);
                ah[mf][2] = *(const uint32_t*)(pa + OSM_AH + 16);
                ah[mf][3] = *(const uint32_t*)(pa + OSM_AH + 8 * ROWB + 16);
                al[mf][0] = *(const uint32_t*)(pa + OSM_AL);
                al[mf][1] = *(const uint32_t*)(pa + OSM_AL + 8 * ROWB);
                al[mf][2] = *(const uint32_t*)(pa + OSM_AL + 16);
                al[mf][3] = *(const uint32_t*)(pa + OSM_AL + 8 * ROWB + 16);
            }
            #pragma unroll
            for (int nf = 0; nf < 8; nf++) {
                const char* pb = smem + (wn + nf * 8 + g) * ROWB + koff;
                uint32_t bh0 = *(const uint32_t*)(pb + OSM_WH);
                uint32_t bh1 = *(const uint32_t*)(pb + OSM_WH + 16);
                mma16816(acc[0][nf], ah[0], bh0, bh1);
                mma16816(acc[1][nf], ah[1], bh0, bh1);
                mma16816(acc[0][nf], al[0], bh0, bh1);
                mma16816(acc[1][nf], al[1], bh0, bh1);
            }
        }
        __syncthreads();
    }

    #pragma unroll
    for (int mf = 0; mf < 2; mf++) {
        float* r0 = Cout + (size_t)(m0 + wm + mf * 16 + g) * 256 + n0 + wn;
        float* r8 = r0 + (size_t)8 * 256;
        #pragma unroll
        for (int nf = 0; nf < 8; nf++) {
            float2 bv = *(const float2*)(bias + n0 + wn + nf * 8 + t2);
            float2 o0, o1;
            o0.x = acc[mf][nf][0] + bv.x;  o0.y = acc[mf][nf][1] + bv.y;
            o1.x = acc[mf][nf][2] + bv.x;  o1.y = acc[mf][nf][3] + bv.y;
            *(float2*)(r0 + nf * 8 + t2) = o0;
            *(float2*)(r8 + nf * 8 + t2) = o1;
        }
    }
}

// ---------------- softmax + deformable sampling (128 thr, half2 channels) ----------------
__global__ void __launch_bounds__(128)
sample_kernel(const float* __restrict__ refp, float* __restrict__ mid)
{
    const int bq  = blockIdx.x;
    const int b   = bq / Q_;
    const int tid = threadIdx.x;
    const int h   = tid >> 4;
    const int c2  = tid & 15;

    __shared__ float s_off[192];
    __shared__ float s_att[96];
    __shared__ float s_r[4];
    __shared__ int   s_idx[96 * 4];
    __shared__ float s_w[96 * 4];

    for (int i = tid; i < 192; i += 128) s_off[i] = g_offs[bq * 192 + i];
    if (tid < 96) s_att[tid] = g_attn[bq * 96 + tid];
    if (tid < 4)  s_r[tid]   = refp[bq * 4 + tid];
    __syncthreads();

    if (tid < 8) {
        float mx = -1e30f;
        #pragma unroll
        for (int p = 0; p < TP_; p++) mx = fmaxf(mx, s_att[tid * TP_ + p]);
        float sm = 0.f;
        #pragma unroll
        for (int p = 0; p < TP_; p++) {
            float e = expf(s_att[tid * TP_ + p] - mx);
            s_att[tid * TP_ + p] = e;
            sm += e;
        }
        float inv = 1.f / sm;
        #pragma unroll
        for (int p = 0; p < TP_; p++) s_att[tid * TP_ + p] *= inv;
    }
    __syncthreads();

    if (tid < 96) {
        const int p = tid % TP_;
        const int l = p >> 2;
        const int Wd = (l == 0) ? 80 : (l == 1) ? 40 : 20;
        const int st = (l == 0) ? 0  : (l == 1) ? 6400 : 8000;
        const float rx = s_r[0], ry = s_r[1];
        const float rw = s_r[2] * 0.125f;
        const float rh = s_r[3] * 0.125f;
        const float a  = s_att[tid];

        const float gx = (rx + s_off[tid * 2 + 0] * rw) * (float)Wd - 0.5f;
        const float gy = (ry + s_off[tid * 2 + 1] * rh) * (float)Wd - 0.5f;
        const float x0f = floorf(gx), y0f = floorf(gy);
        const float fx = gx - x0f, fy = gy - y0f;
        const int ix0 = (int)x0f, iy0 = (int)y0f;
        const int ix1 = ix0 + 1,  iy1 = iy0 + 1;
        const bool vx0 = (ix0 >= 0) & (ix0 < Wd);
        const bool vx1 = (ix1 >= 0) & (ix1 < Wd);
        const bool vy0 = (iy0 >= 0) & (iy0 < Wd);
        const bool vy1 = (iy1 >= 0) & (iy1 < Wd);
        const int ix0c = min(max(ix0, 0), Wd - 1);
        const int ix1c = min(max(ix1, 0), Wd - 1);
        const int iy0c = min(max(iy0, 0), Wd - 1);
        const int iy1c = min(max(iy1, 0), Wd - 1);

        s_w[tid * 4 + 0] = (vx0 & vy0) ? (1.f - fx) * (1.f - fy) * a : 0.f;
        s_w[tid * 4 + 1] = (vx1 & vy0) ? fx * (1.f - fy) * a : 0.f;
        s_w[tid * 4 + 2] = (vx0 & vy1) ? (1.f - fx) * fy * a : 0.f;
        s_w[tid * 4 + 3] = (vx1 & vy1) ? fx * fy * a : 0.f;
        s_idx[tid * 4 + 0] = (st + iy0c * Wd + ix0c) * D_;
        s_idx[tid * 4 + 1] = (st + iy0c * Wd + ix1c) * D_;
        s_idx[tid * 4 + 2] = (st + iy1c * Wd + ix0c) * D_;
        s_idx[tid * 4 + 3] = (st + iy1c * Wd + ix1c) * D_;
    }
    __syncthreads();

    const __half* vb = g_value + (size_t)b * S_ * D_ + h * C_ + c2 * 2;

    float accx = 0.f, accy = 0.f;
    #pragma unroll
    for (int p = 0; p < TP_; p++) {
        const int e = (h * TP_ + p) * 4;
        const int   i0 = s_idx[e], i1 = s_idx[e + 1], i2 = s_idx[e + 2], i3 = s_idx[e + 3];
        const float w0 = s_w[e],   w1 = s_w[e + 1],   w2 = s_w[e + 2],   w3 = s_w[e + 3];
        float2 v0 = __half22float2(*(const __half2*)(vb + i0));
        float2 v1 = __half22float2(*(const __half2*)(vb + i1));
        float2 v2 = __half22float2(*(const __half2*)(vb + i2));
        float2 v3 = __half22float2(*(const __half2*)(vb + i3));
        accx = fmaf(w0, v0.x, accx);  accy = fmaf(w0, v0.y, accy);
        accx = fmaf(w1, v1.x, accx);  accy = fmaf(w1, v1.y, accy);
        accx = fmaf(w2, v2.x, accx);  accy = fmaf(w2, v2.y, accy);
        accx = fmaf(w3, v3.x, accx);  accy = fmaf(w3, v3.y, accy);
    }
    *(float2*)(mid + (size_t)bq * D_ + h * C_ + c2 * 2) = make_float2(accx, accy);
}

// ---------------- launcher ----------------
extern "C" void kernel_launch(void* const* d_in, const int* in_sizes, int n_in,
                              void* d_out, int out_size)
{
    (void)in_sizes; (void)n_in; (void)out_size;
    const float* hidden = (const float*)d_in[0];
    const float* enc    = (const float*)d_in[1];
    const float* refp   = (const float*)d_in[2];
    const float* W_off  = (const float*)d_in[3];
    const float* b_off  = (const float*)d_in[4];
    const float* W_attn = (const float*)d_in[5];
    const float* b_attn = (const float*)d_in[6];
    const float* W_val  = (const float*)d_in[7];
    const float* b_val  = (const float*)d_in[8];
    const float* W_out  = (const float*)d_in[9];
    const float* b_out  = (const float*)d_in[10];
    float* out = (float*)d_out;

    __half* p_value;
    float*  p_mid;
    cudaGetSymbolAddress((void**)&p_value, g_value);
    cudaGetSymbolAddress((void**)&p_mid,   g_mid);

    cudaFuncSetAttribute(fused_main,   cudaFuncAttributeMaxDynamicSharedMemorySize, VSM_TOT);
    cudaFuncSetAttribute(out_gemm_mma, cudaFuncAttributeMaxDynamicSharedMemorySize, OSM_TOT);

    // 0) transpose + fp16-convert W_val (z=0) and W_out (z=1)
    prep_w_kernel<<<dim3(8, 8, 2), dim3(32, 8)>>>(W_val, W_out);

    // 1) fused: qproj blocks (first 225) + pipelined value GEMM blocks (2100)
    fused_main<<<NQPROJ + B_ * S_ / 128, 512, VSM_TOT>>>(
        enc, b_val, p_value, hidden, W_off, b_off, W_attn, b_attn);

    // 2) softmax + bilinear gather + weighted sum
    sample_kernel<<<B_ * Q_, 128>>>(refp, p_mid);

    // 3) output projection on tensor cores (2-product)
    out_gemm_mma<<<dim3(B_ * Q_ / 128, 2), 256, OSM_TOT>>>(p_mid, b_out, out);
}

// round 17
// speedup vs baseline: 1.3712x; 1.0052x over previous
#include <cuda_runtime.h>
#include <cuda_fp16.h>
#include <math.h>
#include <stdint.h>

#define B_   32
#define Q_   300
#define D_   256
#define H_   8
#define C_   32
#define S_   8400
#define TP_  12

// ---------------- scratch (no allocations allowed) ----------------
__device__ __half g_value[(long long)B_ * S_ * D_];  // 137 MB (fp16 value)
__device__ float  g_offs [B_ * Q_ * 192];
__device__ float  g_attn [B_ * Q_ * 96];
__device__ float  g_mid  [B_ * Q_ * D_];
__device__ __half g_wT    [D_ * D_];                 // W_val^T fp16
__device__ __half g_woT   [D_ * D_];                 // W_out^T fp16

__device__ __forceinline__ uint32_t smem_u32(const void* p) {
    uint32_t a;
    asm("{ .reg .u64 t; cvta.to.shared.u64 t, %1; cvt.u32.u64 %0, t; }" : "=r"(a) : "l"(p));
    return a;
}
__device__ __forceinline__ void cp_async16(uint32_t dst, const void* src) {
    asm volatile("cp.async.cg.shared.global [%0], [%1], 16;" :: "r"(dst), "l"(src));
}
__device__ __forceinline__ void ldsm_x4(uint32_t& r0, uint32_t& r1, uint32_t& r2,
                                        uint32_t& r3, uint32_t addr) {
    asm volatile("ldmatrix.sync.aligned.m8n8.x4.shared.b16 {%0,%1,%2,%3}, [%4];"
        : "=r"(r0), "=r"(r1), "=r"(r2), "=r"(r3) : "r"(addr));
}

// ---------------- prep: transpose weights -> fp16 (z=0: W_val, z=1: W_out) ----------------
__global__ void prep_w_kernel(const float* __restrict__ Wv, const float* __restrict__ Wo) {
    __shared__ float t[32][33];
    const float* src = blockIdx.z ? Wo : Wv;
    int bx = blockIdx.x, by = blockIdx.y;
    int tx = threadIdx.x, ty = threadIdx.y;   // 32 x 8
    #pragma unroll
    for (int i = 0; i < 32; i += 8)
        t[ty + i][tx] = src[(size_t)(by * 32 + ty + i) * 256 + bx * 32 + tx];
    __syncthreads();
    #pragma unroll
    for (int i = 0; i < 32; i += 8) {
        int n = bx * 32 + ty + i;
        int k = by * 32 + tx;
        float v = t[tx][ty + i];
        __half h = __float2half_rn(v);
        if (blockIdx.z == 0) g_wT [(size_t)n * 256 + k] = h;
        else                 g_woT[(size_t)n * 256 + k] = h;
    }
}

// ---------------- mma helper ----------------
__device__ __forceinline__ void mma16816(float* c, const uint32_t* a,
                                         uint32_t b0, uint32_t b1) {
    asm volatile(
        "mma.sync.aligned.m16n8k16.row.col.f32.f16.f16.f32 "
        "{%0,%1,%2,%3}, {%4,%5,%6,%7}, {%8,%9}, {%0,%1,%2,%3};"
        : "+f"(c[0]), "+f"(c[1]), "+f"(c[2]), "+f"(c[3])
        : "r"(a[0]), "r"(a[1]), "r"(a[2]), "r"(a[3]), "r"(b0), "r"(b1));
}

#define ROWB 144                 // 64 halves + 8 pad
#define ABUF0 0
#define ABUF1 18432
#define WBUF0 36864
#define WBUF1 73728
#define VSM_TOT 110592           // fused kernel: 2xA + 2xW ping-pong
// out-proj (M64 x N128): A hi 64x144 = 9216, A lo 9216, W 128x144 = 18432
#define OSM_AH 0
#define OSM_AL 9216
#define OSM_WH 18432
#define OSM_TOT 36864
#define NQPROJ 225

// ---------------- fused: qproj (fp32 FFMA) + pipelined value GEMM (R10 config) ----
__global__ void __launch_bounds__(512, 1)
fused_main(const float* __restrict__ enc, const float* __restrict__ b_val,
           __half* __restrict__ Cout,
           const float* __restrict__ hidden,
           const float* __restrict__ W_off, const float* __restrict__ b_off,
           const float* __restrict__ W_attn, const float* __restrict__ b_attn)
{
    extern __shared__ char smem[];
    const int tid = threadIdx.x;

    if (blockIdx.x < NQPROJ) {
        // ================= qproj: (9600,256)@(256,288), 512 threads, 8x4 micro ====
        const int K = 256, M = B_ * Q_, N = 288;
        float (*As)[132] = (float(*)[132])(smem);
        float (*Ws)[128] = (float(*)[128])(smem + 16 * 132 * 4);

        const int tx  = tid & 31;
        const int ty  = tid >> 5;
        const int m0  = (blockIdx.x / 3) * 128;
        const int n0  = (blockIdx.x % 3) * 128;

        float acc[8][4];
        #pragma unroll
        for (int i = 0; i < 8; i++)
            #pragma unroll
            for (int j = 0; j < 4; j++) acc[i][j] = 0.f;

        for (int kt = 0; kt < K; kt += 16) {
            {
                int row = tid >> 2;
                int kq  = (tid & 3) * 4;
                float4 v = make_float4(0.f, 0.f, 0.f, 0.f);
                int gr = m0 + row;
                if (gr < M)
                    v = *(const float4*)(hidden + (size_t)gr * K + kt + kq);
                As[kq + 0][row] = v.x;
                As[kq + 1][row] = v.y;
                As[kq + 2][row] = v.z;
                As[kq + 3][row] = v.w;
            }
            {
                int kr  = tid >> 5;
                int c4  = (tid & 31) * 4;
                float4 v = make_float4(0.f, 0.f, 0.f, 0.f);
                int gc = n0 + c4;
                if (gc < 192)
                    v = *(const float4*)(W_off + (size_t)(kt + kr) * 192 + gc);
                else if (gc < N)
                    v = *(const float4*)(W_attn + (size_t)(kt + kr) * 96 + gc - 192);
                *(float4*)&Ws[kr][c4] = v;
            }
            __syncthreads();

            #pragma unroll
            for (int k = 0; k < 16; k++) {
                float a[8], b[4];
                *(float4*)&a[0] = *(const float4*)&As[k][ty * 8];
                *(float4*)&a[4] = *(const float4*)&As[k][ty * 8 + 4];
                *(float4*)&b[0] = *(const float4*)&Ws[k][tx * 4];
                #pragma unroll
                for (int i = 0; i < 8; i++)
                    #pragma unroll
                    for (int j = 0; j < 4; j++)
                        acc[i][j] = fmaf(a[i], b[j], acc[i][j]);
            }
            __syncthreads();
        }

        #pragma unroll
        for (int i = 0; i < 8; i++) {
            int gr = m0 + ty * 8 + i;
            if (gr >= M) continue;
            int gc = n0 + tx * 4;
            if (gc < 192) {
                float4 o;
                o.x = acc[i][0] + b_off[gc + 0];
                o.y = acc[i][1] + b_off[gc + 1];
                o.z = acc[i][2] + b_off[gc + 2];
                o.w = acc[i][3] + b_off[gc + 3];
                *(float4*)(g_offs + (size_t)gr * 192 + gc) = o;
            } else if (gc < N) {
                int ga = gc - 192;
                float4 o;
                o.x = acc[i][0] + b_attn[ga + 0];
                o.y = acc[i][1] + b_attn[ga + 1];
                o.z = acc[i][2] + b_attn[ga + 2];
                o.w = acc[i][3] + b_attn[ga + 3];
                *(float4*)(g_attn + (size_t)gr * 96 + ga) = o;
            }
        }
        return;
    }

    // ================= value GEMM: 128M x 256N, pipelined, ldmatrix (R10) =========
    const int id  = blockIdx.x - NQPROJ;
    const int wid = tid >> 5, lid = tid & 31;
    const int g   = lid >> 2;
    const int t2  = (lid & 3) * 2;
    const int wm  = (wid & 3) * 32;
    const int wn  = (wid >> 2) * 64;
    const int m0  = id * 128;

    const uint32_t sb = smem_u32(smem);
    const int arow = tid >> 2, aq = tid & 3;
    const int wrow = tid >> 1, whlf = tid & 1;

    const float* asrc = enc + (size_t)(m0 + arow) * 256 + aq * 16;
    const char*  wsrc = (const char*)g_wT + (size_t)wrow * 512 + whlf * 64;
    const uint32_t adst[2] = { sb + ABUF0 + (uint32_t)(arow * ROWB + aq * 32),
                               sb + ABUF1 + (uint32_t)(arow * ROWB + aq * 32) };
    const uint32_t wdst[2] = { sb + WBUF0 + (uint32_t)(wrow * ROWB + whlf * 64),
                               sb + WBUF1 + (uint32_t)(wrow * ROWB + whlf * 64) };

    const uint32_t lmoff = (uint32_t)(((lid & 7) + ((lid >> 3) & 1) * 8) * ROWB
                                      + (lid >> 4) * 16);
    const uint32_t albase[2] = { sb + ABUF0 + (uint32_t)(wm * ROWB) + lmoff,
                                 sb + ABUF1 + (uint32_t)(wm * ROWB) + lmoff };
    const uint32_t wlbase[2] = { sb + WBUF0 + (uint32_t)(wn * ROWB) + lmoff,
                                 sb + WBUF1 + (uint32_t)(wn * ROWB) + lmoff };

    float acc[2][8][4];
    #pragma unroll
    for (int i = 0; i < 2; i++)
        #pragma unroll
        for (int j = 0; j < 8; j++)
            #pragma unroll
            for (int k = 0; k < 4; k++) acc[i][j][k] = 0.f;

    // ---- prologue: chunk 0 ----
    #pragma unroll
    for (int j = 0; j < 4; j++)
        cp_async16(wdst[0] + j * 16, wsrc + j * 16);
    asm volatile("cp.async.commit_group;");
    {
        float4 av[4];
        #pragma unroll
        for (int j = 0; j < 4; j++)
            av[j] = *(const float4*)(asrc + j * 4);
        #pragma unroll
        for (int j = 0; j < 2; j++) {
            __half2 p0 = __floats2half2_rn(av[2*j].x, av[2*j].y);
            __half2 p1 = __floats2half2_rn(av[2*j].z, av[2*j].w);
            __half2 p2 = __floats2half2_rn(av[2*j+1].x, av[2*j+1].y);
            __half2 p3 = __floats2half2_rn(av[2*j+1].z, av[2*j+1].w);
            uint4 pk = make_uint4(*(uint32_t*)&p0, *(uint32_t*)&p1,
                                  *(uint32_t*)&p2, *(uint32_t*)&p3);
            asm volatile("st.shared.v4.b32 [%0], {%1,%2,%3,%4};"
                :: "r"(adst[0] + j * 16), "r"(pk.x), "r"(pk.y), "r"(pk.z), "r"(pk.w));
        }
    }
    asm volatile("cp.async.wait_group 0;" ::: "memory");
    __syncthreads();

    for (int ch = 0; ch < 4; ch++) {
        const int cur = ch & 1, nxt = cur ^ 1;
        float4 av[4];
        if (ch < 3) {
            #pragma unroll
            for (int j = 0; j < 4; j++)
                cp_async16(wdst[nxt] + j * 16, wsrc + (ch + 1) * 128 + j * 16);
            asm volatile("cp.async.commit_group;");
            #pragma unroll
            for (int j = 0; j < 4; j++)
                av[j] = *(const float4*)(asrc + (ch + 1) * 64 + j * 4);
        }

        // ---- MMA on current buffers via ldmatrix ----
        #pragma unroll
        for (int ks = 0; ks < 4; ks++) {
            uint32_t ah[2][4];
            ldsm_x4(ah[0][0], ah[0][1], ah[0][2], ah[0][3], albase[cur] + ks * 32);
            ldsm_x4(ah[1][0], ah[1][1], ah[1][2], ah[1][3],
                    albase[cur] + 16 * ROWB + ks * 32);
            uint32_t bw[8][2];
            #pragma unroll
            for (int nfp = 0; nfp < 4; nfp++) {
                uint32_t q0, q1, q2, q3;
                ldsm_x4(q0, q1, q2, q3, wlbase[cur] + nfp * 16 * ROWB + ks * 32);
                bw[2*nfp][0]   = q0;  bw[2*nfp][1]   = q2;
                bw[2*nfp+1][0] = q1;  bw[2*nfp+1][1] = q3;
            }
            #pragma unroll
            for (int nf = 0; nf < 8; nf++) {
                mma16816(acc[0][nf], ah[0], bw[nf][0], bw[nf][1]);
                mma16816(acc[1][nf], ah[1], bw[nf][0], bw[nf][1]);
            }
        }

        if (ch < 3) {
            #pragma unroll
            for (int j = 0; j < 2; j++) {
                __half2 p0 = __floats2half2_rn(av[2*j].x, av[2*j].y);
                __half2 p1 = __floats2half2_rn(av[2*j].z, av[2*j].w);
                __half2 p2 = __floats2half2_rn(av[2*j+1].x, av[2*j+1].y);
                __half2 p3 = __floats2half2_rn(av[2*j+1].z, av[2*j+1].w);
                uint4 pk = make_uint4(*(uint32_t*)&p0, *(uint32_t*)&p1,
                                      *(uint32_t*)&p2, *(uint32_t*)&p3);
                asm volatile("st.shared.v4.b32 [%0], {%1,%2,%3,%4};"
                    :: "r"(adst[nxt] + j * 16), "r"(pk.x), "r"(pk.y), "r"(pk.z), "r"(pk.w));
            }
            asm volatile("cp.async.wait_group 0;" ::: "memory");
        }
        __syncthreads();
    }

    // ---- epilogue: +bias, convert fp16, store ----
    #pragma unroll
    for (int mf = 0; mf < 2; mf++) {
        __half* r0 = Cout + (size_t)(m0 + wm + mf * 16 + g) * 256 + wn;
        __half* r8 = r0 + (size_t)8 * 256;
        #pragma unroll
        for (int nf = 0; nf < 8; nf++) {
            float2 bv = *(const float2*)(b_val + wn + nf * 8 + t2);
            *(__half2*)(r0 + nf * 8 + t2) =
                __floats2half2_rn(acc[mf][nf][0] + bv.x, acc[mf][nf][1] + bv.y);
            *(__half2*)(r8 + nf * 8 + t2) =
                __floats2half2_rn(acc[mf][nf][2] + bv.x, acc[mf][nf][3] + bv.y);
        }
    }
}

// ---------------- out projection: mma fp16 2-product, M64 x N128 tiles ----------------
__global__ void __launch_bounds__(256, 2)
out_gemm_mma(const float* __restrict__ A, const float* __restrict__ bias,
             float* __restrict__ Cout)
{
    extern __shared__ char smem[];
    const int tid = threadIdx.x;
    const int wid = tid >> 5, lid = tid & 31;
    const int g   = lid >> 2;
    const int t2  = (lid & 3) * 2;
    const int wm  = (wid & 1) * 32;      // 2 M-warps  -> 64 rows
    const int wn  = (wid >> 1) * 32;     // 4 N-warps  -> 128 cols
    const int m0  = blockIdx.x * 64;
    const int n0  = blockIdx.y * 128;

    float acc[2][4][4];
    #pragma unroll
    for (int i = 0; i < 2; i++)
        #pragma unroll
        for (int j = 0; j < 4; j++)
            #pragma unroll
            for (int k = 0; k < 4; k++) acc[i][j][k] = 0.f;

    const int arow  = tid >> 2;          // 0..63 (A rows)
    const int aq    = tid & 3;           // quarter: 16 floats
    const int wrow  = tid >> 1;          // 0..127 (W rows)
    const int whlf  = tid & 1;

    for (int ch = 0; ch < 4; ch++) {
        {   // A: 64 rows x 64 fp32 -> hi/lo fp16
            const float4* ap = (const float4*)(A + (size_t)(m0 + arow) * 256 + ch * 64 + aq * 16);
            char* ahb = smem + OSM_AH + arow * ROWB + aq * 32;
            char* alb = smem + OSM_AL + arow * ROWB + aq * 32;
            #pragma unroll
            for (int j = 0; j < 2; j++) {
                float4 v0 = ap[2 * j], v1 = ap[2 * j + 1];
                float f[8] = {v0.x, v0.y, v0.z, v0.w, v1.x, v1.y, v1.z, v1.w};
                unsigned hb[8], lb[8];
                #pragma unroll
                for (int e = 0; e < 8; e++) {
                    __half h = __float2half_rn(f[e]);
                    hb[e] = __half_as_ushort(h);
                    lb[e] = __half_as_ushort(__float2half_rn(f[e] - __half2float(h)));
                }
                *(uint4*)(ahb + j * 16) = make_uint4(hb[0] | (hb[1] << 16), hb[2] | (hb[3] << 16),
                                                    hb[4] | (hb[5] << 16), hb[6] | (hb[7] << 16));
                *(uint4*)(alb + j * 16) = make_uint4(lb[0] | (lb[1] << 16), lb[2] | (lb[3] << 16),
                                                    lb[4] | (lb[5] << 16), lb[6] | (lb[7] << 16));
            }
        }
        {   // W: 128 rows x 64 halves
            const uint4* wh = (const uint4*)((const char*)g_woT + (size_t)(n0 + wrow) * 512 + ch * 128 + whlf * 64);
            char* whb = smem + OSM_WH + wrow * ROWB + whlf * 64;
            #pragma unroll
            for (int j = 0; j < 4; j++)
                *(uint4*)(whb + j * 16) = wh[j];
        }
        __syncthreads();

        #pragma unroll
        for (int ks = 0; ks < 4; ks++) {
            const int koff = (ks * 16 + t2) * 2;
            uint32_t ah[2][4], al[2][4];
            #pragma unroll
            for (int mf = 0; mf < 2; mf++) {
                const char* pa = smem + (wm + mf * 16 + g) * ROWB + koff;
                ah[mf][0] = *(const uint32_t*)(pa + OSM_AH);
                ah[mf][1] = *(const uint32_t*)(pa + OSM_AH + 8 * ROWB);
                ah[mf][2] = *(const uint32_t*)(pa + OSM_AH + 16);
                ah[mf][3] = *(const uint32_t*)(pa + OSM_AH + 8 * ROWB + 16);
                al[mf][0] = *(const uint32_t*)(pa + OSM_AL);
                al[mf][1] = *(const uint32_t*)(pa + OSM_AL + 8 * ROWB);
                al[mf][2] = *(const uint32_t*)(pa + OSM_AL + 16);
                al[mf][3] = *(const uint32_t*)(pa + OSM_AL + 8 * ROWB + 16);
            }
            #pragma unroll
            for (int nf = 0; nf < 4; nf++) {
                const char* pb = smem + OSM_WH + (wn + nf * 8 + g) * ROWB + koff;
                uint32_t bh0 = *(const uint32_t*)(pb);
                uint32_t bh1 = *(const uint32_t*)(pb + 16);
                mma16816(acc[0][nf], ah[0], bh0, bh1);
                mma16816(acc[1][nf], ah[1], bh0, bh1);
                mma16816(acc[0][nf], al[0], bh0, bh1);
                mma16816(acc[1][nf], al[1], bh0, bh1);
            }
        }
        __syncthreads();
    }

    #pragma unroll
    for (int mf = 0; mf < 2; mf++) {
        float* r0 = Cout + (size_t)(m0 + wm + mf * 16 + g) * 256 + n0 + wn;
        float* r8 = r0 + (size_t)8 * 256;
        #pragma unroll
        for (int nf = 0; nf < 4; nf++) {
            float2 bv = *(const float2*)(bias + n0 + wn + nf * 8 + t2);
            float2 o0, o1;
            o0.x = acc[mf][nf][0] + bv.x;  o0.y = acc[mf][nf][1] + bv.y;
            o1.x = acc[mf][nf][2] + bv.x;  o1.y = acc[mf][nf][3] + bv.y;
            *(float2*)(r0 + nf * 8 + t2) = o0;
            *(float2*)(r8 + nf * 8 + t2) = o1;
        }
    }
}

// ---------------- softmax + deformable sampling: 2 queries/block, 256 thr ----------------
__global__ void __launch_bounds__(256)
sample_kernel(const float* __restrict__ refp, float* __restrict__ mid)
{
    const int qsub = threadIdx.x >> 7;        // 0/1: which query in the pair
    const int tid  = threadIdx.x & 127;       // local thread within query
    const int bq   = blockIdx.x * 2 + qsub;
    const int b    = bq / Q_;
    const int h    = tid >> 4;
    const int c2   = tid & 15;

    __shared__ float s_off[2][192];
    __shared__ float s_att[2][96];
    __shared__ float s_r[2][4];
    __shared__ int   s_idx[2][96 * 4];
    __shared__ float s_w[2][96 * 4];

    for (int i = tid; i < 192; i += 128) s_off[qsub][i] = g_offs[bq * 192 + i];
    if (tid < 96) s_att[qsub][tid] = g_attn[bq * 96 + tid];
    if (tid < 4)  s_r[qsub][tid]   = refp[bq * 4 + tid];
    __syncthreads();

    if (tid < 8) {   // softmax over 12 points per head
        float mx = -1e30f;
        #pragma unroll
        for (int p = 0; p < TP_; p++) mx = fmaxf(mx, s_att[qsub][tid * TP_ + p]);
        float sm = 0.f;
        #pragma unroll
        for (int p = 0; p < TP_; p++) {
            float e = expf(s_att[qsub][tid * TP_ + p] - mx);
            s_att[qsub][tid * TP_ + p] = e;
            sm += e;
        }
        float inv = 1.f / sm;
        #pragma unroll
        for (int p = 0; p < TP_; p++) s_att[qsub][tid * TP_ + p] *= inv;
    }
    __syncthreads();

    if (tid < 96) {  // one thread per (head, point): compute 4 taps
        const int p = tid % TP_;
        const int l = p >> 2;
        const int Wd = (l == 0) ? 80 : (l == 1) ? 40 : 20;
        const int st = (l == 0) ? 0  : (l == 1) ? 6400 : 8000;
        const float rx = s_r[qsub][0], ry = s_r[qsub][1];
        const float rw = s_r[qsub][2] * 0.125f;
        const float rh = s_r[qsub][3] * 0.125f;
        const float a  = s_att[qsub][tid];

        const float gx = (rx + s_off[qsub][tid * 2 + 0] * rw) * (float)Wd - 0.5f;
        const float gy = (ry + s_off[qsub][tid * 2 + 1] * rh) * (float)Wd - 0.5f;
        const float x0f = floorf(gx), y0f = floorf(gy);
        const float fx = gx - x0f, fy = gy - y0f;
        const int ix0 = (int)x0f, iy0 = (int)y0f;
        const int ix1 = ix0 + 1,  iy1 = iy0 + 1;
        const bool vx0 = (ix0 >= 0) & (ix0 < Wd);
        const bool vx1 = (ix1 >= 0) & (ix1 < Wd);
        const bool vy0 = (iy0 >= 0) & (iy0 < Wd);
        const bool vy1 = (iy1 >= 0) & (iy1 < Wd);
        const int ix0c = min(max(ix0, 0), Wd - 1);
        const int ix1c = min(max(ix1, 0), Wd - 1);
        const int iy0c = min(max(iy0, 0), Wd - 1);
        const int iy1c = min(max(iy1, 0), Wd - 1);

        s_w[qsub][tid * 4 + 0] = (vx0 & vy0) ? (1.f - fx) * (1.f - fy) * a : 0.f;
        s_w[qsub][tid * 4 + 1] = (vx1 & vy0) ? fx * (1.f - fy) * a : 0.f;
        s_w[qsub][tid * 4 + 2] = (vx0 & vy1) ? (1.f - fx) * fy * a : 0.f;
        s_w[qsub][tid * 4 + 3] = (vx1 & vy1) ? fx * fy * a : 0.f;
        s_idx[qsub][tid * 4 + 0] = (st + iy0c * Wd + ix0c) * D_;
        s_idx[qsub][tid * 4 + 1] = (st + iy0c * Wd + ix1c) * D_;
        s_idx[qsub][tid * 4 + 2] = (st + iy1c * Wd + ix0c) * D_;
        s_idx[qsub][tid * 4 + 3] = (st + iy1c * Wd + ix1c) * D_;
    }
    __syncthreads();

    const __half* vb = g_value + (size_t)b * S_ * D_ + h * C_ + c2 * 2;

    float accx = 0.f, accy = 0.f;
    #pragma unroll
    for (int p = 0; p < TP_; p++) {
        const int e = (h * TP_ + p) * 4;
        const int   i0 = s_idx[qsub][e],     i1 = s_idx[qsub][e + 1];
        const int   i2 = s_idx[qsub][e + 2], i3 = s_idx[qsub][e + 3];
        const float w0 = s_w[qsub][e],       w1 = s_w[qsub][e + 1];
        const float w2 = s_w[qsub][e + 2],   w3 = s_w[qsub][e + 3];
        float2 v0 = __half22float2(*(const __half2*)(vb + i0));
        float2 v1 = __half22float2(*(const __half2*)(vb + i1));
        float2 v2 = __half22float2(*(const __half2*)(vb + i2));
        float2 v3 = __half22float2(*(const __half2*)(vb + i3));
        accx = fmaf(w0, v0.x, accx);  accy = fmaf(w0, v0.y, accy);
        accx = fmaf(w1, v1.x, accx);  accy = fmaf(w1, v1.y, accy);
        accx = fmaf(w2, v2.x, accx);  accy = fmaf(w2, v2.y, accy);
        accx = fmaf(w3, v3.x, accx);  accy = fmaf(w3, v3.y, accy);
    }
    *(float2*)(mid + (size_t)bq * D_ + h * C_ + c2 * 2) = make_float2(accx, accy);
}

// ---------------- launcher ----------------
extern "C" void kernel_launch(void* const* d_in, const int* in_sizes, int n_in,
                              void* d_out, int out_size)
{
    (void)in_sizes; (void)n_in; (void)out_size;
    const float* hidden = (const float*)d_in[0];
    const float* enc    = (const float*)d_in[1];
    const float* refp   = (const float*)d_in[2];
    const float* W_off  = (const float*)d_in[3];
    const float* b_off  = (const float*)d_in[4];
    const float* W_attn = (const float*)d_in[5];
    const float* b_attn = (const float*)d_in[6];
    const float* W_val  = (const float*)d_in[7];
    const float* b_val  = (const float*)d_in[8];
    const float* W_out  = (const float*)d_in[9];
    const float* b_out  = (const float*)d_in[10];
    float* out = (float*)d_out;

    __half* p_value;
    float*  p_mid;
    cudaGetSymbolAddress((void**)&p_value, g_value);
    cudaGetSymbolAddress((void**)&p_mid,   g_mid);

    cudaFuncSetAttribute(fused_main,   cudaFuncAttributeMaxDynamicSharedMemorySize, VSM_TOT);
    cudaFuncSetAttribute(out_gemm_mma, cudaFuncAttributeMaxDynamicSharedMemorySize, OSM_TOT);

    // 0) transpose + fp16-convert W_val (z=0) and W_out (z=1)
    prep_w_kernel<<<dim3(8, 8, 2), dim3(32, 8)>>>(W_val, W_out);

    // 1) fused: qproj blocks (first 225) + pipelined value GEMM blocks (2100)
    fused_main<<<NQPROJ + B_ * S_ / 128, 512, VSM_TOT>>>(
        enc, b_val, p_value, hidden, W_off, b_off, W_attn, b_attn);

    // 2) softmax + bilinear gather + weighted sum (2 queries per block)
    sample_kernel<<<B_ * Q_ / 2, 256>>>(refp, p_mid);

    // 3) output projection on tensor cores (2-product, M64xN128 tiles)
    out_gemm_mma<<<dim3(B_ * Q_ / 64, 2), 256, OSM_TOT>>>(p_mid, b_out, out);
}